// round 2
// baseline (speedup 1.0000x reference)
#include <cuda_runtime.h>
#include <cuda_bf16.h>

// ---------------- static scratch (no runtime allocation allowed) ----------------
#define MAXN 100000
#define MAXE 1200000

__device__ float g_bufH[(size_t)MAXN * 256];   // GEMM output h = x@W
__device__ float g_bufO[(size_t)MAXN * 256];   // aggregated conv output
__device__ float g_dinv[MAXN];                 // deg -> d^{-1/2} (in place)
__device__ float g_norm[MAXE];                 // per-edge norm coefficient
__device__ float g_pool[256 * 320];            // segment sums
__device__ float g_cnt[256];                   // segment counts
__device__ float g_fc1[256 * 1024];            // hidden MLP activations

// ---------------- degree / norm ----------------
__global__ void deg_init_kernel(float* deg, int N) {
    int i = blockIdx.x * blockDim.x + threadIdx.x;
    if (i < N) deg[i] = 1.0f;   // self-loop weight
}

__global__ void deg_acc_kernel(const int* __restrict__ dst, const float* __restrict__ w,
                               float* __restrict__ deg, int E) {
    int e = blockIdx.x * blockDim.x + threadIdx.x;
    if (e < E) atomicAdd(&deg[dst[e]], w[e]);
}

__global__ void dinv_kernel(float* deg, int N) {
    int i = blockIdx.x * blockDim.x + threadIdx.x;
    if (i < N) deg[i] = rsqrtf(deg[i]);   // deg >= 1 always (self-loop)
}

__global__ void norm_kernel(const int* __restrict__ src, const int* __restrict__ dst,
                            const float* __restrict__ w, const float* __restrict__ dinv,
                            float* __restrict__ norm, int E) {
    int e = blockIdx.x * blockDim.x + threadIdx.x;
    if (e < E) norm[e] = dinv[src[e]] * w[e] * dinv[dst[e]];
}

__global__ void zero_pool_kernel(float* pool, float* cnt) {
    int i = blockIdx.x * blockDim.x + threadIdx.x;
    if (i < 256 * 320) pool[i] = 0.0f;
    if (i < 256) cnt[i] = 0.0f;
}

// ---------------- dense GEMM: H = (relu?)(X) @ W ----------------
// 64x64 block tile, 256 threads, 4x4 micro-tile, BK=16.
template<bool RELU>
__global__ void sgemm_kernel(const float* __restrict__ X, const float* __restrict__ W,
                             float* __restrict__ H, int N, int IN, int OUT) {
    __shared__ float Xs[16][64];
    __shared__ float Ws[16][64];
    int t = threadIdx.x;
    int tx = t & 15, ty = t >> 4;
    int rowBase = blockIdx.x * 64;
    int colBase = blockIdx.y * 64;
    float acc[4][4] = {};

    for (int kb = 0; kb < IN; kb += 16) {
        {   // load X tile [64 rows x 16 k], float4 per thread
            int m  = t >> 2;
            int kq = (t & 3) * 4;
            int r  = rowBase + m;
            float4 f = make_float4(0.f, 0.f, 0.f, 0.f);
            if (r < N)
                f = *reinterpret_cast<const float4*>(&X[(size_t)r * IN + kb + kq]);
            if (RELU) {
                f.x = fmaxf(f.x, 0.f); f.y = fmaxf(f.y, 0.f);
                f.z = fmaxf(f.z, 0.f); f.w = fmaxf(f.w, 0.f);
            }
            Xs[kq + 0][m] = f.x; Xs[kq + 1][m] = f.y;
            Xs[kq + 2][m] = f.z; Xs[kq + 3][m] = f.w;
        }
        {   // load W tile [16 k x 64 cols]
            int k  = t >> 4;
            int nq = (t & 15) * 4;
            float4 g = *reinterpret_cast<const float4*>(&W[(size_t)(kb + k) * OUT + colBase + nq]);
            *reinterpret_cast<float4*>(&Ws[k][nq]) = g;
        }
        __syncthreads();
        #pragma unroll
        for (int k = 0; k < 16; k++) {
            float xr[4];
            #pragma unroll
            for (int i = 0; i < 4; i++) xr[i] = Xs[k][ty * 4 + i];
            float4 wv = *reinterpret_cast<const float4*>(&Ws[k][tx * 4]);
            float wr[4] = {wv.x, wv.y, wv.z, wv.w};
            #pragma unroll
            for (int i = 0; i < 4; i++)
                #pragma unroll
                for (int j = 0; j < 4; j++)
                    acc[i][j] += xr[i] * wr[j];
        }
        __syncthreads();
    }
    #pragma unroll
    for (int i = 0; i < 4; i++) {
        int r = rowBase + ty * 4 + i;
        if (r < N) {
            float4 o = make_float4(acc[i][0], acc[i][1], acc[i][2], acc[i][3]);
            *reinterpret_cast<float4*>(&H[(size_t)r * OUT + colBase + tx * 4]) = o;
        }
    }
}

// ---------------- conv init: Out = b + dinv^2 * h  (bias + self-loop term) ----------------
template<int OUT>
__global__ void conv_init_kernel(const float* __restrict__ H, const float* __restrict__ b,
                                 const float* __restrict__ dinv, float* __restrict__ Out, int N) {
    const int G = OUT / 4;
    int idx = blockIdx.x * blockDim.x + threadIdx.x;
    if (idx >= N * G) return;
    int i = idx / G, g = idx % G;
    float di = dinv[i];
    float sl = di * di;
    float4 h  = *reinterpret_cast<const float4*>(&H[(size_t)i * OUT + g * 4]);
    float4 bb = *reinterpret_cast<const float4*>(&b[g * 4]);
    float4 o = make_float4(bb.x + sl * h.x, bb.y + sl * h.y,
                           bb.z + sl * h.z, bb.w + sl * h.w);
    *reinterpret_cast<float4*>(&Out[(size_t)i * OUT + g * 4]) = o;
}

// ---------------- edge scatter: Out[dst] += norm * h[src]  (float4 global atomics) ----------------
template<int OUT>
__global__ void edge_scatter_kernel(const int* __restrict__ src, const int* __restrict__ dst,
                                    const float* __restrict__ norm, const float* __restrict__ H,
                                    float* __restrict__ Out, int E) {
    const int G = OUT / 4;
    int idx = blockIdx.x * blockDim.x + threadIdx.x;
    if (idx >= E * G) return;
    int e = idx / G, g = idx % G;
    float nr = norm[e];
    int s = src[e], d = dst[e];
    float4 h = *reinterpret_cast<const float4*>(&H[(size_t)s * OUT + g * 4]);
    float4 v = make_float4(nr * h.x, nr * h.y, nr * h.z, nr * h.w);
    atomicAdd(reinterpret_cast<float4*>(&Out[(size_t)d * OUT + g * 4]), v);
}

// ---------------- pooling: segment sums of [relu(conv3) | feature] + counts ----------------
__global__ void pool_kernel(const float* __restrict__ conv3, const float* __restrict__ feat,
                            const int* __restrict__ pb, float* __restrict__ pool,
                            float* __restrict__ cnt, int N) {
    int idx = blockIdx.x * blockDim.x + threadIdx.x;
    if (idx >= N * 80) return;
    int i = idx / 80, g = idx % 80;
    int s = pb[i];
    float4 v;
    if (g < 64) {
        v = *reinterpret_cast<const float4*>(&conv3[(size_t)i * 256 + g * 4]);
        v.x = fmaxf(v.x, 0.f); v.y = fmaxf(v.y, 0.f);
        v.z = fmaxf(v.z, 0.f); v.w = fmaxf(v.w, 0.f);
    } else {
        v = *reinterpret_cast<const float4*>(&feat[(size_t)i * 64 + (g - 64) * 4]);
    }
    atomicAdd(reinterpret_cast<float4*>(&pool[s * 320 + g * 4]), v);
    if (g == 0) atomicAdd(&cnt[s], 1.0f);
}

// ---------------- MLP head ----------------
__global__ void fc1_kernel(const float* __restrict__ pool, const float* __restrict__ cnt,
                           const float* __restrict__ Wf1, const float* __restrict__ bf1,
                           float* __restrict__ fc1) {
    __shared__ float srow[320];
    __shared__ float sinv;
    int row = blockIdx.y;
    int col = blockIdx.x * 256 + threadIdx.x;
    for (int k = threadIdx.x; k < 320; k += 256) srow[k] = pool[row * 320 + k];
    if (threadIdx.x == 0) sinv = 1.0f / fmaxf(cnt[row], 1.0f);
    __syncthreads();
    float acc = 0.f;
    #pragma unroll 8
    for (int k = 0; k < 320; k++) acc += srow[k] * Wf1[(size_t)k * 1024 + col];
    float v = acc * sinv + bf1[col];
    fc1[(size_t)row * 1024 + col] = fmaxf(v, 0.f);
}

__global__ void fc2_kernel(const float* __restrict__ fc1, const float* __restrict__ Wf2,
                           const float* __restrict__ bf2, float* __restrict__ out) {
    int row = blockIdx.x;
    float a = 0.f;
    for (int j = threadIdx.x; j < 1024; j += 256)
        a += fc1[(size_t)row * 1024 + j] * Wf2[j];
    __shared__ float red[256];
    red[threadIdx.x] = a;
    __syncthreads();
    for (int s = 128; s > 0; s >>= 1) {
        if (threadIdx.x < s) red[threadIdx.x] += red[threadIdx.x + s];
        __syncthreads();
    }
    if (threadIdx.x == 0) out[row] = red[0] + bf2[0];
}

// ---------------- launch ----------------
extern "C" void kernel_launch(void* const* d_in, const int* in_sizes, int n_in,
                              void* d_out, int out_size) {
    const float* feature = (const float*)d_in[0];
    const int*   ei      = (const int*)d_in[1];
    const float* weight  = (const float*)d_in[2];
    const int*   pb      = (const int*)d_in[3];
    const float* W1 = (const float*)d_in[4];  const float* b1  = (const float*)d_in[5];
    const float* W2 = (const float*)d_in[6];  const float* b2  = (const float*)d_in[7];
    const float* W3 = (const float*)d_in[8];  const float* b3  = (const float*)d_in[9];
    const float* Wf1 = (const float*)d_in[10]; const float* bf1 = (const float*)d_in[11];
    const float* Wf2 = (const float*)d_in[12]; const float* bf2 = (const float*)d_in[13];
    float* out = (float*)d_out;

    int N = in_sizes[0] / 64;
    int E = in_sizes[2];
    const int* src = ei;
    const int* dst = ei + E;

    float *bufH, *bufO, *dinv, *nrm, *pool, *cnt, *fc1;
    cudaGetSymbolAddress((void**)&bufH, g_bufH);
    cudaGetSymbolAddress((void**)&bufO, g_bufO);
    cudaGetSymbolAddress((void**)&dinv, g_dinv);
    cudaGetSymbolAddress((void**)&nrm,  g_norm);
    cudaGetSymbolAddress((void**)&pool, g_pool);
    cudaGetSymbolAddress((void**)&cnt,  g_cnt);
    cudaGetSymbolAddress((void**)&fc1,  g_fc1);

    const int T = 256;
    deg_init_kernel<<<(N + T - 1) / T, T>>>(dinv, N);
    deg_acc_kernel<<<(E + T - 1) / T, T>>>(dst, weight, dinv, E);
    dinv_kernel<<<(N + T - 1) / T, T>>>(dinv, N);
    norm_kernel<<<(E + T - 1) / T, T>>>(src, dst, weight, dinv, nrm, E);
    zero_pool_kernel<<<(256 * 320 + T - 1) / T, T>>>(pool, cnt);

    // layer 1: 64 -> 64
    sgemm_kernel<false><<<dim3((N + 63) / 64, 1), 256>>>(feature, W1, bufH, N, 64, 64);
    conv_init_kernel<64><<<(N * 16 + T - 1) / T, T>>>(bufH, b1, dinv, bufO, N);
    edge_scatter_kernel<64><<<(E * 16 + T - 1) / T, T>>>(src, dst, nrm, bufH, bufO, E);

    // layer 2: 64 -> 128 (relu on input)
    sgemm_kernel<true><<<dim3((N + 63) / 64, 2), 256>>>(bufO, W2, bufH, N, 64, 128);
    conv_init_kernel<128><<<(N * 32 + T - 1) / T, T>>>(bufH, b2, dinv, bufO, N);
    edge_scatter_kernel<128><<<(E * 32 + T - 1) / T, T>>>(src, dst, nrm, bufH, bufO, E);

    // layer 3: 128 -> 256 (relu on input)
    sgemm_kernel<true><<<dim3((N + 63) / 64, 4), 256>>>(bufO, W3, bufH, N, 128, 256);
    conv_init_kernel<256><<<(N * 64 + T - 1) / T, T>>>(bufH, b3, dinv, bufO, N);
    edge_scatter_kernel<256><<<(E * 64 + T - 1) / T, T>>>(src, dst, nrm, bufH, bufO, E);

    // pooling + MLP head
    pool_kernel<<<(N * 80 + T - 1) / T, T>>>(bufO, feature, pb, pool, cnt, N);
    fc1_kernel<<<dim3(4, 256), 256>>>(pool, cnt, Wf1, bf1, fc1);
    fc2_kernel<<<256, 256>>>(fc1, Wf2, bf2, out);
}

// round 7
// speedup vs baseline: 1.5279x; 1.5279x over previous
#include <cuda_runtime.h>
#include <cuda_bf16.h>

// ---------------- static scratch (no runtime allocation allowed) ----------------
#define MAXN 100000
#define MAXE 1200000

__device__ float g_bufH[(size_t)MAXN * 256];   // GEMM output h = x@W
__device__ float g_bufO[(size_t)MAXN * 256];   // aggregated conv output
__device__ float g_dinv[MAXN];                 // deg -> d^{-1/2} (in place)
__device__ int   g_rowptr[MAXN + 1];           // CSR row pointer (by dst)
__device__ int   g_woff[MAXN + 1];             // write cursor for placement
__device__ int   g_hist[MAXN];                 // per-dst degree histogram
__device__ int   g_bsums[128];                 // block sums for scan
__device__ int   g_csr_src[MAXE];              // src ids sorted by dst
__device__ float g_csr_norm[MAXE];             // edge norm sorted by dst
__device__ float g_pool[256 * 320];            // segment sums
__device__ float g_cnt[256];                   // segment counts
__device__ float g_fc1[256 * 1024];            // hidden MLP activations

// ---------------- degree / dinv ----------------
__global__ void deg_init_kernel(float* deg, int* hist, int N) {
    int i = blockIdx.x * blockDim.x + threadIdx.x;
    if (i < N) { deg[i] = 1.0f; hist[i] = 0; }   // self-loop weight; zero hist
}

__global__ void deg_acc_kernel(const int* __restrict__ dst, const float* __restrict__ w,
                               float* __restrict__ deg, int* __restrict__ hist, int E) {
    int e = blockIdx.x * blockDim.x + threadIdx.x;
    if (e < E) {
        int d = dst[e];
        atomicAdd(&deg[d], w[e]);
        atomicAdd(&hist[d], 1);
    }
}

__global__ void dinv_kernel(float* deg, int N) {
    int i = blockIdx.x * blockDim.x + threadIdx.x;
    if (i < N) deg[i] = rsqrtf(deg[i]);   // deg >= 1 always (self-loop)
}

// ---------------- scan: hist -> rowptr (exclusive) ----------------
__global__ void scan_block_kernel(const int* __restrict__ hist, int* __restrict__ rowptr,
                                  int* __restrict__ bsums, int N) {
    __shared__ int sh[1024];
    int i = blockIdx.x * 1024 + threadIdx.x;
    int v = (i < N) ? hist[i] : 0;
    sh[threadIdx.x] = v;
    __syncthreads();
    for (int off = 1; off < 1024; off <<= 1) {
        int t = (threadIdx.x >= off) ? sh[threadIdx.x - off] : 0;
        __syncthreads();
        sh[threadIdx.x] += t;
        __syncthreads();
    }
    if (i < N) rowptr[i] = sh[threadIdx.x] - v;        // exclusive within block
    if (threadIdx.x == 1023) bsums[blockIdx.x] = sh[1023];
}

__global__ void scan_sums_kernel(int* bsums, int nb) {
    __shared__ int sh[128];
    int v = (threadIdx.x < nb) ? bsums[threadIdx.x] : 0;
    sh[threadIdx.x] = v;
    __syncthreads();
    for (int off = 1; off < 128; off <<= 1) {
        int t = (threadIdx.x >= off) ? sh[threadIdx.x - off] : 0;
        __syncthreads();
        sh[threadIdx.x] += t;
        __syncthreads();
    }
    if (threadIdx.x < nb) bsums[threadIdx.x] = sh[threadIdx.x] - v;   // exclusive
}

__global__ void add_off_kernel(int* __restrict__ rowptr, const int* __restrict__ bsums,
                               int* __restrict__ woff, int N, int E) {
    int i = blockIdx.x * blockDim.x + threadIdx.x;
    if (i < N) {
        int r = rowptr[i] + bsums[i >> 10];
        rowptr[i] = r;
        woff[i] = r;
    }
    if (i == N) rowptr[N] = E;
}

// ---------------- placement: scatter edges into CSR order, norm computed inline ----------------
__global__ void place_kernel(const int* __restrict__ src, const int* __restrict__ dst,
                             const float* __restrict__ w, const float* __restrict__ dinv,
                             int* __restrict__ woff, int* __restrict__ csr_src,
                             float* __restrict__ csr_norm, int E) {
    int e = blockIdx.x * blockDim.x + threadIdx.x;
    if (e >= E) return;
    int s = src[e], d = dst[e];
    float nr = dinv[s] * w[e] * dinv[d];
    int pos = atomicAdd(&woff[d], 1);
    csr_src[pos] = s;
    csr_norm[pos] = nr;
}

__global__ void zero_pool_kernel(float* pool, float* cnt) {
    int i = blockIdx.x * blockDim.x + threadIdx.x;
    if (i < 256 * 320) pool[i] = 0.0f;
    if (i < 256) cnt[i] = 0.0f;
}

// ---------------- dense GEMM: H = (relu?)(X) @ W ----------------
// 64x64 block tile, 256 threads, 4x4 micro-tile, BK=16.
template<bool RELU>
__global__ void sgemm_kernel(const float* __restrict__ X, const float* __restrict__ W,
                             float* __restrict__ H, int N, int IN, int OUT) {
    __shared__ float Xs[16][64];
    __shared__ float Ws[16][64];
    int t = threadIdx.x;
    int tx = t & 15, ty = t >> 4;
    int rowBase = blockIdx.x * 64;
    int colBase = blockIdx.y * 64;
    float acc[4][4] = {};

    for (int kb = 0; kb < IN; kb += 16) {
        {   // load X tile [64 rows x 16 k], float4 per thread
            int m  = t >> 2;
            int kq = (t & 3) * 4;
            int r  = rowBase + m;
            float4 f = make_float4(0.f, 0.f, 0.f, 0.f);
            if (r < N)
                f = *reinterpret_cast<const float4*>(&X[(size_t)r * IN + kb + kq]);
            if (RELU) {
                f.x = fmaxf(f.x, 0.f); f.y = fmaxf(f.y, 0.f);
                f.z = fmaxf(f.z, 0.f); f.w = fmaxf(f.w, 0.f);
            }
            Xs[kq + 0][m] = f.x; Xs[kq + 1][m] = f.y;
            Xs[kq + 2][m] = f.z; Xs[kq + 3][m] = f.w;
        }
        {   // load W tile [16 k x 64 cols]
            int k  = t >> 4;
            int nq = (t & 15) * 4;
            float4 g = *reinterpret_cast<const float4*>(&W[(size_t)(kb + k) * OUT + colBase + nq]);
            *reinterpret_cast<float4*>(&Ws[k][nq]) = g;
        }
        __syncthreads();
        #pragma unroll
        for (int k = 0; k < 16; k++) {
            float xr[4];
            #pragma unroll
            for (int i = 0; i < 4; i++) xr[i] = Xs[k][ty * 4 + i];
            float4 wv = *reinterpret_cast<const float4*>(&Ws[k][tx * 4]);
            float wr[4] = {wv.x, wv.y, wv.z, wv.w};
            #pragma unroll
            for (int i = 0; i < 4; i++)
                #pragma unroll
                for (int j = 0; j < 4; j++)
                    acc[i][j] += xr[i] * wr[j];
        }
        __syncthreads();
    }
    #pragma unroll
    for (int i = 0; i < 4; i++) {
        int r = rowBase + ty * 4 + i;
        if (r < N) {
            float4 o = make_float4(acc[i][0], acc[i][1], acc[i][2], acc[i][3]);
            *reinterpret_cast<float4*>(&H[(size_t)r * OUT + colBase + tx * 4]) = o;
        }
    }
}

// ---------------- CSR gather aggregation: Out[i] = b + dinv_i^2 h[i] + sum_e norm_e h[src_e] ----------------
template<int OUT>
__global__ void gather_kernel(const int* __restrict__ rowptr, const int* __restrict__ csr_src,
                              const float* __restrict__ csr_norm, const float* __restrict__ H,
                              const float* __restrict__ b, const float* __restrict__ dinv,
                              float* __restrict__ Out, int N) {
    const int G = OUT / 4;                // threads per node
    const int NPB = 256 / G;              // nodes per block
    int lane = threadIdx.x % G;
    int node = blockIdx.x * NPB + threadIdx.x / G;
    if (node >= N) return;

    int beg = rowptr[node];
    int end = rowptr[node + 1];
    float di = dinv[node];
    float sl = di * di;

    float4 h  = *reinterpret_cast<const float4*>(&H[(size_t)node * OUT + lane * 4]);
    float4 bb = *reinterpret_cast<const float4*>(&b[lane * 4]);
    float4 acc = make_float4(bb.x + sl * h.x, bb.y + sl * h.y,
                             bb.z + sl * h.z, bb.w + sl * h.w);

    int k = beg;
    for (; k + 1 < end; k += 2) {
        int s0 = csr_src[k];     float n0 = csr_norm[k];
        int s1 = csr_src[k + 1]; float n1 = csr_norm[k + 1];
        float4 h0 = *reinterpret_cast<const float4*>(&H[(size_t)s0 * OUT + lane * 4]);
        float4 h1 = *reinterpret_cast<const float4*>(&H[(size_t)s1 * OUT + lane * 4]);
        acc.x += n0 * h0.x + n1 * h1.x;
        acc.y += n0 * h0.y + n1 * h1.y;
        acc.z += n0 * h0.z + n1 * h1.z;
        acc.w += n0 * h0.w + n1 * h1.w;
    }
    if (k < end) {
        int s0 = csr_src[k]; float n0 = csr_norm[k];
        float4 h0 = *reinterpret_cast<const float4*>(&H[(size_t)s0 * OUT + lane * 4]);
        acc.x += n0 * h0.x; acc.y += n0 * h0.y;
        acc.z += n0 * h0.z; acc.w += n0 * h0.w;
    }
    *reinterpret_cast<float4*>(&Out[(size_t)node * OUT + lane * 4]) = acc;
}

// ---------------- pooling: segment sums of [relu(conv3) | feature] + counts ----------------
__global__ void pool_kernel(const float* __restrict__ conv3, const float* __restrict__ feat,
                            const int* __restrict__ pb, float* __restrict__ pool,
                            float* __restrict__ cnt, int N) {
    int idx = blockIdx.x * blockDim.x + threadIdx.x;
    if (idx >= N * 80) return;
    int i = idx / 80, g = idx % 80;
    int s = pb[i];
    float4 v;
    if (g < 64) {
        v = *reinterpret_cast<const float4*>(&conv3[(size_t)i * 256 + g * 4]);
        v.x = fmaxf(v.x, 0.f); v.y = fmaxf(v.y, 0.f);
        v.z = fmaxf(v.z, 0.f); v.w = fmaxf(v.w, 0.f);
    } else {
        v = *reinterpret_cast<const float4*>(&feat[(size_t)i * 64 + (g - 64) * 4]);
    }
    atomicAdd(reinterpret_cast<float4*>(&pool[s * 320 + g * 4]), v);
    if (g == 0) atomicAdd(&cnt[s], 1.0f);
}

// ---------------- MLP head ----------------
__global__ void fc1_kernel(const float* __restrict__ pool, const float* __restrict__ cnt,
                           const float* __restrict__ Wf1, const float* __restrict__ bf1,
                           float* __restrict__ fc1) {
    __shared__ float srow[320];
    __shared__ float sinv;
    int row = blockIdx.y;
    int col = blockIdx.x * 256 + threadIdx.x;
    for (int k = threadIdx.x; k < 320; k += 256) srow[k] = pool[row * 320 + k];
    if (threadIdx.x == 0) sinv = 1.0f / fmaxf(cnt[row], 1.0f);
    __syncthreads();
    float acc = 0.f;
    #pragma unroll 8
    for (int k = 0; k < 320; k++) acc += srow[k] * Wf1[(size_t)k * 1024 + col];
    float v = acc * sinv + bf1[col];
    fc1[(size_t)row * 1024 + col] = fmaxf(v, 0.f);
}

__global__ void fc2_kernel(const float* __restrict__ fc1, const float* __restrict__ Wf2,
                           const float* __restrict__ bf2, float* __restrict__ out) {
    int row = blockIdx.x;
    float a = 0.f;
    for (int j = threadIdx.x; j < 1024; j += 256)
        a += fc1[(size_t)row * 1024 + j] * Wf2[j];
    __shared__ float red[256];
    red[threadIdx.x] = a;
    __syncthreads();
    for (int s = 128; s > 0; s >>= 1) {
        if (threadIdx.x < s) red[threadIdx.x] += red[threadIdx.x + s];
        __syncthreads();
    }
    if (threadIdx.x == 0) out[row] = red[0] + bf2[0];
}

// ---------------- launch ----------------
extern "C" void kernel_launch(void* const* d_in, const int* in_sizes, int n_in,
                              void* d_out, int out_size) {
    const float* feature = (const float*)d_in[0];
    const int*   ei      = (const int*)d_in[1];
    const float* weight  = (const float*)d_in[2];
    const int*   pb      = (const int*)d_in[3];
    const float* W1 = (const float*)d_in[4];  const float* b1  = (const float*)d_in[5];
    const float* W2 = (const float*)d_in[6];  const float* b2  = (const float*)d_in[7];
    const float* W3 = (const float*)d_in[8];  const float* b3  = (const float*)d_in[9];
    const float* Wf1 = (const float*)d_in[10]; const float* bf1 = (const float*)d_in[11];
    const float* Wf2 = (const float*)d_in[12]; const float* bf2 = (const float*)d_in[13];
    float* out = (float*)d_out;

    int N = in_sizes[0] / 64;
    int E = in_sizes[2];
    const int* src = ei;
    const int* dst = ei + E;

    float *bufH, *bufO, *dinv, *pool, *cnt, *fc1, *csr_norm;
    int *rowptr, *woff, *hist, *bsums, *csr_src;
    cudaGetSymbolAddress((void**)&bufH, g_bufH);
    cudaGetSymbolAddress((void**)&bufO, g_bufO);
    cudaGetSymbolAddress((void**)&dinv, g_dinv);
    cudaGetSymbolAddress((void**)&rowptr, g_rowptr);
    cudaGetSymbolAddress((void**)&woff, g_woff);
    cudaGetSymbolAddress((void**)&hist, g_hist);
    cudaGetSymbolAddress((void**)&bsums, g_bsums);
    cudaGetSymbolAddress((void**)&csr_src, g_csr_src);
    cudaGetSymbolAddress((void**)&csr_norm, g_csr_norm);
    cudaGetSymbolAddress((void**)&pool, g_pool);
    cudaGetSymbolAddress((void**)&cnt,  g_cnt);
    cudaGetSymbolAddress((void**)&fc1,  g_fc1);

    const int T = 256;
    int nb = (N + 1023) / 1024;

    // degrees + histogram
    deg_init_kernel<<<(N + T - 1) / T, T>>>(dinv, hist, N);
    deg_acc_kernel<<<(E + T - 1) / T, T>>>(dst, weight, dinv, hist, E);
    dinv_kernel<<<(N + T - 1) / T, T>>>(dinv, N);

    // CSR build: scan + placement (norm fused into placement)
    scan_block_kernel<<<nb, 1024>>>(hist, rowptr, bsums, N);
    scan_sums_kernel<<<1, 128>>>(bsums, nb);
    add_off_kernel<<<(N + 1 + T - 1) / T, T>>>(rowptr, bsums, woff, N, E);
    place_kernel<<<(E + T - 1) / T, T>>>(src, dst, weight, dinv, woff, csr_src, csr_norm, E);

    zero_pool_kernel<<<(256 * 320 + T - 1) / T, T>>>(pool, cnt);

    // layer 1: 64 -> 64
    sgemm_kernel<false><<<dim3((N + 63) / 64, 1), 256>>>(feature, W1, bufH, N, 64, 64);
    gather_kernel<64><<<(N * 16 + 255) / 256, 256>>>(rowptr, csr_src, csr_norm, bufH, b1, dinv, bufO, N);

    // layer 2: 64 -> 128 (relu on input)
    sgemm_kernel<true><<<dim3((N + 63) / 64, 2), 256>>>(bufO, W2, bufH, N, 64, 128);
    gather_kernel<128><<<(N * 32 + 255) / 256, 256>>>(rowptr, csr_src, csr_norm, bufH, b2, dinv, bufO, N);

    // layer 3: 128 -> 256 (relu on input)
    sgemm_kernel<true><<<dim3((N + 63) / 64, 4), 256>>>(bufO, W3, bufH, N, 128, 256);
    gather_kernel<256><<<(N * 64 + 255) / 256, 256>>>(rowptr, csr_src, csr_norm, bufH, b3, dinv, bufO, N);

    // pooling + MLP head
    pool_kernel<<<(N * 80 + T - 1) / T, T>>>(bufO, feature, pb, pool, cnt, N);
    fc1_kernel<<<dim3(4, 256), 256>>>(pool, cnt, Wf1, bf1, fc1);
    fc2_kernel<<<256, 256>>>(fc1, Wf2, bf2, out);
}

// round 8
// speedup vs baseline: 2.0510x; 1.3424x over previous
#include <cuda_runtime.h>
#include <cuda_bf16.h>
#include <cstdint>

// ---------------- static scratch (no runtime allocation allowed) ----------------
#define MAXN 100000
#define MAXE 1200000

__device__ float g_bufH[(size_t)MAXN * 256];   // h = relu(y@W + b) per layer (final: h3 [N][256])
__device__ float g_bufY[(size_t)MAXN * 128];   // y = aggregated input features
__device__ float g_dinv[MAXN];                 // deg -> d^{-1/2} (in place)
__device__ int   g_rowptr[MAXN + 1];           // CSR row pointer (by dst)
__device__ int   g_woff[MAXN + 1];             // write cursor for placement
__device__ int   g_hist[MAXN];                 // per-dst degree histogram
__device__ int   g_bsums[128];                 // block sums for scan
__device__ int   g_csr_src[MAXE];              // src ids sorted by dst
__device__ float g_csr_norm[MAXE];             // edge norm sorted by dst
__device__ float g_whi[45056];                 // tf32-hi parts of W1|W2|W3
__device__ float g_wlo[45056];                 // residual parts
__device__ float g_pool[256 * 320];            // segment sums
__device__ float g_cnt[256];                   // segment counts
__device__ float g_fc1[256 * 1024];            // hidden MLP activations

__device__ __forceinline__ uint32_t f32_to_tf32(float f) {
    uint32_t u;
    asm("cvt.rna.tf32.f32 %0, %1;" : "=r"(u) : "f"(f));
    return u;
}

// ---------------- degree / dinv ----------------
__global__ void deg_init_kernel(float* deg, int* hist, int N) {
    int i = blockIdx.x * blockDim.x + threadIdx.x;
    if (i < N) { deg[i] = 1.0f; hist[i] = 0; }   // self-loop weight; zero hist
}

__global__ void deg_acc_kernel(const int* __restrict__ dst, const float* __restrict__ w,
                               float* __restrict__ deg, int* __restrict__ hist, int E) {
    int e = blockIdx.x * blockDim.x + threadIdx.x;
    if (e < E) {
        int d = dst[e];
        atomicAdd(&deg[d], w[e]);
        atomicAdd(&hist[d], 1);
    }
}

__global__ void dinv_kernel(float* deg, int N) {
    int i = blockIdx.x * blockDim.x + threadIdx.x;
    if (i < N) deg[i] = rsqrtf(deg[i]);   // deg >= 1 always (self-loop)
}

// ---------------- scan: hist -> rowptr (exclusive) ----------------
__global__ void scan_block_kernel(const int* __restrict__ hist, int* __restrict__ rowptr,
                                  int* __restrict__ bsums, int N) {
    __shared__ int sh[1024];
    int i = blockIdx.x * 1024 + threadIdx.x;
    int v = (i < N) ? hist[i] : 0;
    sh[threadIdx.x] = v;
    __syncthreads();
    for (int off = 1; off < 1024; off <<= 1) {
        int t = (threadIdx.x >= off) ? sh[threadIdx.x - off] : 0;
        __syncthreads();
        sh[threadIdx.x] += t;
        __syncthreads();
    }
    if (i < N) rowptr[i] = sh[threadIdx.x] - v;        // exclusive within block
    if (threadIdx.x == 1023) bsums[blockIdx.x] = sh[1023];
}

__global__ void scan_sums_kernel(int* bsums, int nb) {
    __shared__ int sh[128];
    int v = (threadIdx.x < nb) ? bsums[threadIdx.x] : 0;
    sh[threadIdx.x] = v;
    __syncthreads();
    for (int off = 1; off < 128; off <<= 1) {
        int t = (threadIdx.x >= off) ? sh[threadIdx.x - off] : 0;
        __syncthreads();
        sh[threadIdx.x] += t;
        __syncthreads();
    }
    if (threadIdx.x < nb) bsums[threadIdx.x] = sh[threadIdx.x] - v;   // exclusive
}

__global__ void add_off_kernel(int* __restrict__ rowptr, const int* __restrict__ bsums,
                               int* __restrict__ woff, int N, int E) {
    int i = blockIdx.x * blockDim.x + threadIdx.x;
    if (i < N) {
        int r = rowptr[i] + bsums[i >> 10];
        rowptr[i] = r;
        woff[i] = r;
    }
    if (i == N) rowptr[N] = E;
}

// ---------------- placement: scatter edges into CSR order, norm computed inline ----------------
__global__ void place_kernel(const int* __restrict__ src, const int* __restrict__ dst,
                             const float* __restrict__ w, const float* __restrict__ dinv,
                             int* __restrict__ woff, int* __restrict__ csr_src,
                             float* __restrict__ csr_norm, int E) {
    int e = blockIdx.x * blockDim.x + threadIdx.x;
    if (e >= E) return;
    int s = src[e], d = dst[e];
    float nr = dinv[s] * w[e] * dinv[d];
    int pos = atomicAdd(&woff[d], 1);
    csr_src[pos] = s;
    csr_norm[pos] = nr;
}

__global__ void zero_pool_kernel(float* pool, float* cnt) {
    int i = blockIdx.x * blockDim.x + threadIdx.x;
    if (i < 256 * 320) pool[i] = 0.0f;
    if (i < 256) cnt[i] = 0.0f;
}

// ---------------- weight split: W = Whi + Wlo, Whi = round-to-nearest tf32 ----------------
__global__ void wsplit_kernel(const float* __restrict__ W, float* __restrict__ hi,
                              float* __restrict__ lo, int n) {
    int i = blockIdx.x * blockDim.x + threadIdx.x;
    if (i >= n) return;
    float w = W[i];
    float h = __uint_as_float(f32_to_tf32(w));
    hi[i] = h;
    lo[i] = w - h;
}

// ---------------- CSR gather aggregation on INPUT features ----------------
// y[i] = dinv_i^2 * x[i] + sum_e norm_e * x[src_e]     (aggregate-then-transform)
template<int IN>
__global__ void gather_kernel(const int* __restrict__ rowptr, const int* __restrict__ csr_src,
                              const float* __restrict__ csr_norm, const float* __restrict__ X,
                              const float* __restrict__ dinv, float* __restrict__ Y, int N) {
    const int G = IN / 4;                 // threads per node
    const int NPB = 256 / G;              // nodes per block
    int lane = threadIdx.x % G;
    int node = blockIdx.x * NPB + threadIdx.x / G;
    if (node >= N) return;

    int beg = rowptr[node];
    int end = rowptr[node + 1];
    float di = dinv[node];
    float sl = di * di;

    float4 x = *reinterpret_cast<const float4*>(&X[(size_t)node * IN + lane * 4]);
    float4 acc = make_float4(sl * x.x, sl * x.y, sl * x.z, sl * x.w);

    int k = beg;
    for (; k + 1 < end; k += 2) {
        int s0 = csr_src[k];     float n0 = csr_norm[k];
        int s1 = csr_src[k + 1]; float n1 = csr_norm[k + 1];
        float4 h0 = *reinterpret_cast<const float4*>(&X[(size_t)s0 * IN + lane * 4]);
        float4 h1 = *reinterpret_cast<const float4*>(&X[(size_t)s1 * IN + lane * 4]);
        acc.x += n0 * h0.x + n1 * h1.x;
        acc.y += n0 * h0.y + n1 * h1.y;
        acc.z += n0 * h0.z + n1 * h1.z;
        acc.w += n0 * h0.w + n1 * h1.w;
    }
    if (k < end) {
        int s0 = csr_src[k]; float n0 = csr_norm[k];
        float4 h0 = *reinterpret_cast<const float4*>(&X[(size_t)s0 * IN + lane * 4]);
        acc.x += n0 * h0.x; acc.y += n0 * h0.y;
        acc.z += n0 * h0.z; acc.w += n0 * h0.w;
    }
    *reinterpret_cast<float4*>(&Y[(size_t)node * IN + lane * 4]) = acc;
}

// ---------------- tf32 tensor-core GEMM: H = relu(A @ (Whi + Wlo) + bias) ----------------
// BM=128, BN=64, BK=32; 256 threads = 8 warps (4 M x 2 N); warp tile 32x32;
// mma.sync.m16n8k8 tf32, two passes (hi/lo) per fragment for W-error compensation.
template<int OUT, int K>
__global__ void __launch_bounds__(256) tf32_gemm_kernel(
    const float* __restrict__ A, const float* __restrict__ Bhi, const float* __restrict__ Blo,
    const float* __restrict__ bias, float* __restrict__ C, int N)
{
    __shared__ float As[32][136];   // [k][m], stride 136 (==8 mod 32 -> conflict-free frags)
    __shared__ float Bh[32][72];    // [k][n], stride 72
    __shared__ float Bl[32][72];

    int t = threadIdx.x;
    int lane = t & 31, w = t >> 5;
    int warpM = w & 3, warpN = w >> 2;
    int rowBase = blockIdx.x * 128;
    int colBase = blockIdx.y * 64;

    float acc[2][4][4];
    #pragma unroll
    for (int a = 0; a < 2; a++)
        #pragma unroll
        for (int b = 0; b < 4; b++)
            #pragma unroll
            for (int c = 0; c < 4; c++) acc[a][b][c] = 0.0f;

    for (int kb = 0; kb < K; kb += 32) {
        // load A tile [128 rows x 32 k], rounding to tf32 at store
        #pragma unroll
        for (int i = 0; i < 4; i++) {
            int lin = t + i * 256;
            int m = lin & 127, ks = lin >> 7;     // ks in 0..7
            int r = rowBase + m;
            float4 v = make_float4(0.f, 0.f, 0.f, 0.f);
            if (r < N) v = *reinterpret_cast<const float4*>(&A[(size_t)r * K + kb + ks * 4]);
            As[ks * 4 + 0][m] = __uint_as_float(f32_to_tf32(v.x));
            As[ks * 4 + 1][m] = __uint_as_float(f32_to_tf32(v.y));
            As[ks * 4 + 2][m] = __uint_as_float(f32_to_tf32(v.z));
            As[ks * 4 + 3][m] = __uint_as_float(f32_to_tf32(v.w));
        }
        // load B tiles [32 k x 64 n], hi and lo
        #pragma unroll
        for (int i = 0; i < 2; i++) {
            int lin = t + i * 256;
            int k = lin >> 4, n4 = (lin & 15) * 4;
            size_t off = (size_t)(kb + k) * OUT + colBase + n4;
            *reinterpret_cast<float4*>(&Bh[k][n4]) = *reinterpret_cast<const float4*>(&Bhi[off]);
            *reinterpret_cast<float4*>(&Bl[k][n4]) = *reinterpret_cast<const float4*>(&Blo[off]);
        }
        __syncthreads();

        #pragma unroll
        for (int kk = 0; kk < 32; kk += 8) {
            int kr = kk + (lane & 3);
            uint32_t af[2][4];
            #pragma unroll
            for (int mt = 0; mt < 2; mt++) {
                int m0 = warpM * 32 + mt * 16 + (lane >> 2);
                af[mt][0] = __float_as_uint(As[kr][m0]);
                af[mt][1] = __float_as_uint(As[kr][m0 + 8]);
                af[mt][2] = __float_as_uint(As[kr + 4][m0]);
                af[mt][3] = __float_as_uint(As[kr + 4][m0 + 8]);
            }
            #pragma unroll
            for (int nt = 0; nt < 4; nt++) {
                int n0 = warpN * 32 + nt * 8 + (lane >> 2);
                uint32_t bh0 = __float_as_uint(Bh[kr][n0]);
                uint32_t bh1 = __float_as_uint(Bh[kr + 4][n0]);
                uint32_t bl0 = __float_as_uint(Bl[kr][n0]);
                uint32_t bl1 = __float_as_uint(Bl[kr + 4][n0]);
                #pragma unroll
                for (int mt = 0; mt < 2; mt++) {
                    float* c = acc[mt][nt];
                    asm volatile(
                        "mma.sync.aligned.m16n8k8.row.col.f32.tf32.tf32.f32 "
                        "{%0,%1,%2,%3}, {%4,%5,%6,%7}, {%8,%9}, {%0,%1,%2,%3};"
                        : "+f"(c[0]), "+f"(c[1]), "+f"(c[2]), "+f"(c[3])
                        : "r"(af[mt][0]), "r"(af[mt][1]), "r"(af[mt][2]), "r"(af[mt][3]),
                          "r"(bh0), "r"(bh1));
                    asm volatile(
                        "mma.sync.aligned.m16n8k8.row.col.f32.tf32.tf32.f32 "
                        "{%0,%1,%2,%3}, {%4,%5,%6,%7}, {%8,%9}, {%0,%1,%2,%3};"
                        : "+f"(c[0]), "+f"(c[1]), "+f"(c[2]), "+f"(c[3])
                        : "r"(af[mt][0]), "r"(af[mt][1]), "r"(af[mt][2]), "r"(af[mt][3]),
                          "r"(bl0), "r"(bl1));
                }
            }
        }
        __syncthreads();
    }

    // epilogue: bias + relu, write fp32
    #pragma unroll
    for (int mt = 0; mt < 2; mt++) {
        #pragma unroll
        for (int nt = 0; nt < 4; nt++) {
            int row = rowBase + warpM * 32 + mt * 16 + (lane >> 2);
            int col = colBase + warpN * 32 + nt * 8 + 2 * (lane & 3);
            float b0 = bias[col], b1 = bias[col + 1];
            float* c = acc[mt][nt];
            if (row < N) {
                float2 o = make_float2(fmaxf(c[0] + b0, 0.f), fmaxf(c[1] + b1, 0.f));
                *reinterpret_cast<float2*>(&C[(size_t)row * OUT + col]) = o;
            }
            if (row + 8 < N) {
                float2 o = make_float2(fmaxf(c[2] + b0, 0.f), fmaxf(c[3] + b1, 0.f));
                *reinterpret_cast<float2*>(&C[(size_t)(row + 8) * OUT + col]) = o;
            }
        }
    }
}

// ---------------- pooling: segment sums of [h3 | feature] + counts (h3 already relu'd) ----------------
__global__ void pool_kernel(const float* __restrict__ conv3, const float* __restrict__ feat,
                            const int* __restrict__ pb, float* __restrict__ pool,
                            float* __restrict__ cnt, int N) {
    int idx = blockIdx.x * blockDim.x + threadIdx.x;
    if (idx >= N * 80) return;
    int i = idx / 80, g = idx % 80;
    int s = pb[i];
    float4 v;
    if (g < 64) {
        v = *reinterpret_cast<const float4*>(&conv3[(size_t)i * 256 + g * 4]);
    } else {
        v = *reinterpret_cast<const float4*>(&feat[(size_t)i * 64 + (g - 64) * 4]);
    }
    atomicAdd(reinterpret_cast<float4*>(&pool[s * 320 + g * 4]), v);
    if (g == 0) atomicAdd(&cnt[s], 1.0f);
}

// ---------------- MLP head ----------------
__global__ void fc1_kernel(const float* __restrict__ pool, const float* __restrict__ cnt,
                           const float* __restrict__ Wf1, const float* __restrict__ bf1,
                           float* __restrict__ fc1) {
    __shared__ float srow[320];
    __shared__ float sinv;
    int row = blockIdx.y;
    int col = blockIdx.x * 256 + threadIdx.x;
    for (int k = threadIdx.x; k < 320; k += 256) srow[k] = pool[row * 320 + k];
    if (threadIdx.x == 0) sinv = 1.0f / fmaxf(cnt[row], 1.0f);
    __syncthreads();
    float acc = 0.f;
    #pragma unroll 8
    for (int k = 0; k < 320; k++) acc += srow[k] * Wf1[(size_t)k * 1024 + col];
    float v = acc * sinv + bf1[col];
    fc1[(size_t)row * 1024 + col] = fmaxf(v, 0.f);
}

__global__ void fc2_kernel(const float* __restrict__ fc1, const float* __restrict__ Wf2,
                           const float* __restrict__ bf2, float* __restrict__ out) {
    int row = blockIdx.x;
    float a = 0.f;
    for (int j = threadIdx.x; j < 1024; j += 256)
        a += fc1[(size_t)row * 1024 + j] * Wf2[j];
    __shared__ float red[256];
    red[threadIdx.x] = a;
    __syncthreads();
    for (int s = 128; s > 0; s >>= 1) {
        if (threadIdx.x < s) red[threadIdx.x] += red[threadIdx.x + s];
        __syncthreads();
    }
    if (threadIdx.x == 0) out[row] = red[0] + bf2[0];
}

// ---------------- launch ----------------
extern "C" void kernel_launch(void* const* d_in, const int* in_sizes, int n_in,
                              void* d_out, int out_size) {
    const float* feature = (const float*)d_in[0];
    const int*   ei      = (const int*)d_in[1];
    const float* weight  = (const float*)d_in[2];
    const int*   pb      = (const int*)d_in[3];
    const float* W1 = (const float*)d_in[4];  const float* b1  = (const float*)d_in[5];
    const float* W2 = (const float*)d_in[6];  const float* b2  = (const float*)d_in[7];
    const float* W3 = (const float*)d_in[8];  const float* b3  = (const float*)d_in[9];
    const float* Wf1 = (const float*)d_in[10]; const float* bf1 = (const float*)d_in[11];
    const float* Wf2 = (const float*)d_in[12]; const float* bf2 = (const float*)d_in[13];
    float* out = (float*)d_out;

    int N = in_sizes[0] / 64;
    int E = in_sizes[2];
    const int* src = ei;
    const int* dst = ei + E;

    float *bufH, *bufY, *dinv, *pool, *cnt, *fc1, *csr_norm, *whi, *wlo;
    int *rowptr, *woff, *hist, *bsums, *csr_src;
    cudaGetSymbolAddress((void**)&bufH, g_bufH);
    cudaGetSymbolAddress((void**)&bufY, g_bufY);
    cudaGetSymbolAddress((void**)&dinv, g_dinv);
    cudaGetSymbolAddress((void**)&rowptr, g_rowptr);
    cudaGetSymbolAddress((void**)&woff, g_woff);
    cudaGetSymbolAddress((void**)&hist, g_hist);
    cudaGetSymbolAddress((void**)&bsums, g_bsums);
    cudaGetSymbolAddress((void**)&csr_src, g_csr_src);
    cudaGetSymbolAddress((void**)&csr_norm, g_csr_norm);
    cudaGetSymbolAddress((void**)&whi, g_whi);
    cudaGetSymbolAddress((void**)&wlo, g_wlo);
    cudaGetSymbolAddress((void**)&pool, g_pool);
    cudaGetSymbolAddress((void**)&cnt,  g_cnt);
    cudaGetSymbolAddress((void**)&fc1,  g_fc1);

    const int T = 256;
    int nb = (N + 1023) / 1024;

    // weight splits (hi = tf32-round, lo = residual); offsets: W1@0, W2@4096, W3@12288
    wsplit_kernel<<<(4096 + T - 1) / T, T>>>(W1, whi, wlo, 64 * 64);
    wsplit_kernel<<<(8192 + T - 1) / T, T>>>(W2, whi + 4096, wlo + 4096, 64 * 128);
    wsplit_kernel<<<(32768 + T - 1) / T, T>>>(W3, whi + 12288, wlo + 12288, 128 * 256);

    // degrees + histogram
    deg_init_kernel<<<(N + T - 1) / T, T>>>(dinv, hist, N);
    deg_acc_kernel<<<(E + T - 1) / T, T>>>(dst, weight, dinv, hist, E);
    dinv_kernel<<<(N + T - 1) / T, T>>>(dinv, N);

    // CSR build: scan + placement (norm fused into placement)
    scan_block_kernel<<<nb, 1024>>>(hist, rowptr, bsums, N);
    scan_sums_kernel<<<1, 128>>>(bsums, nb);
    add_off_kernel<<<(N + 1 + T - 1) / T, T>>>(rowptr, bsums, woff, N, E);
    place_kernel<<<(E + T - 1) / T, T>>>(src, dst, weight, dinv, woff, csr_src, csr_norm, E);

    zero_pool_kernel<<<(256 * 320 + T - 1) / T, T>>>(pool, cnt);

    int gb128 = (N + 127) / 128;

    // layer 1: y1 = agg(feature) [N,64]; h1 = relu(y1@W1 + b1) [N,64]
    gather_kernel<64><<<(N * 16 + 255) / 256, 256>>>(rowptr, csr_src, csr_norm, feature, dinv, bufY, N);
    tf32_gemm_kernel<64, 64><<<dim3(gb128, 1), 256>>>(bufY, whi, wlo, b1, bufH, N);

    // layer 2: y2 = agg(h1) [N,64]; h2 = relu(y2@W2 + b2) [N,128]
    gather_kernel<64><<<(N * 16 + 255) / 256, 256>>>(rowptr, csr_src, csr_norm, bufH, dinv, bufY, N);
    tf32_gemm_kernel<128, 64><<<dim3(gb128, 2), 256>>>(bufY, whi + 4096, wlo + 4096, b2, bufH, N);

    // layer 3: y3 = agg(h2) [N,128]; h3 = relu(y3@W3 + b3) [N,256]
    gather_kernel<128><<<(N * 32 + 255) / 256, 256>>>(rowptr, csr_src, csr_norm, bufH, dinv, bufY, N);
    tf32_gemm_kernel<256, 128><<<dim3(gb128, 4), 256>>>(bufY, whi + 12288, wlo + 12288, b3, bufH, N);

    // pooling + MLP head
    pool_kernel<<<(N * 80 + T - 1) / T, T>>>(bufH, feature, pb, pool, cnt, N);
    fc1_kernel<<<dim3(4, 256), 256>>>(pool, cnt, Wf1, bf1, fc1);
    fc2_kernel<<<256, 256>>>(fc1, Wf2, bf2, out);
}

// round 10
// speedup vs baseline: 2.4119x; 1.1759x over previous
#include <cuda_runtime.h>
#include <cuda_bf16.h>
#include <cstdint>

// ---------------- static scratch (no runtime allocation allowed) ----------------
#define MAXN 100000
#define MAXE 1200000

__device__ float g_bufH[(size_t)MAXN * 256];   // h = relu(y@W + b) per layer
__device__ float g_bufY[(size_t)MAXN * 128];   // y = aggregated input features
__device__ float g_dinv[MAXN];                 // deg -> d^{-1/2} (in place)
__device__ int   g_rowptr[MAXN + 1];           // CSR row pointer (by dst)
__device__ int   g_woff[MAXN + 1];             // write cursor for placement
__device__ int   g_hist[MAXN];                 // per-dst degree histogram
__device__ int   g_bsums[128];                 // block sums for scan
__device__ int2  g_csr[MAXE];                  // packed (src, norm) sorted by dst
__device__ int   g_segstart[257];              // pooling segment boundaries
__device__ float g_whi[45056];                 // tf32-hi parts of W1|W2|W3
__device__ float g_wlo[45056];                 // residual parts
__device__ float g_pool[4 * 256 * 320];        // segment partial sums (4 slabs)
__device__ float g_fc1[256 * 1024];            // hidden MLP activations

__device__ __forceinline__ uint32_t f32_to_tf32(float f) {
    uint32_t u;
    asm("cvt.rna.tf32.f32 %0, %1;" : "=r"(u) : "f"(f));
    return u;
}

// ---------------- degree / histogram init ----------------
__global__ void deg_init_kernel(float* deg, int* hist, int N) {
    int i = blockIdx.x * blockDim.x + threadIdx.x;
    if (i < N) { deg[i] = 1.0f; hist[i] = 0; }   // self-loop weight; zero hist
}

__global__ void deg_acc_kernel(const int* __restrict__ dst, const float* __restrict__ w,
                               float* __restrict__ deg, int* __restrict__ hist, int E) {
    int e = blockIdx.x * blockDim.x + threadIdx.x;
    if (e < E) {
        int d = dst[e];
        atomicAdd(&deg[d], w[e]);
        atomicAdd(&hist[d], 1);
    }
}

// ---------------- scan: hist -> rowptr (exclusive); dinv folded in ----------------
__global__ void scan_block_kernel(const int* __restrict__ hist, int* __restrict__ rowptr,
                                  int* __restrict__ bsums, float* __restrict__ deg, int N) {
    __shared__ int sh[1024];
    int i = blockIdx.x * 1024 + threadIdx.x;
    int v = (i < N) ? hist[i] : 0;
    if (i < N) deg[i] = rsqrtf(deg[i]);          // deg -> d^{-1/2} (deg >= 1)
    sh[threadIdx.x] = v;
    __syncthreads();
    for (int off = 1; off < 1024; off <<= 1) {
        int t = (threadIdx.x >= off) ? sh[threadIdx.x - off] : 0;
        __syncthreads();
        sh[threadIdx.x] += t;
        __syncthreads();
    }
    if (i < N) rowptr[i] = sh[threadIdx.x] - v;        // exclusive within block
    if (threadIdx.x == 1023) bsums[blockIdx.x] = sh[1023];
}

__global__ void scan_sums_kernel(int* bsums, int nb) {
    __shared__ int sh[128];
    int v = (threadIdx.x < nb) ? bsums[threadIdx.x] : 0;
    sh[threadIdx.x] = v;
    __syncthreads();
    for (int off = 1; off < 128; off <<= 1) {
        int t = (threadIdx.x >= off) ? sh[threadIdx.x - off] : 0;
        __syncthreads();
        sh[threadIdx.x] += t;
        __syncthreads();
    }
    if (threadIdx.x < nb) bsums[threadIdx.x] = sh[threadIdx.x] - v;   // exclusive
}

__global__ void add_off_kernel(int* __restrict__ rowptr, const int* __restrict__ bsums,
                               int* __restrict__ woff, int N, int E) {
    int i = blockIdx.x * blockDim.x + threadIdx.x;
    if (i < N) {
        int r = rowptr[i] + bsums[i >> 10];
        rowptr[i] = r;
        woff[i] = r;
    }
    if (i == N) rowptr[N] = E;
}

// ---------------- placement: packed (src, norm) into CSR order ----------------
__global__ void place_kernel(const int* __restrict__ src, const int* __restrict__ dst,
                             const float* __restrict__ w, const float* __restrict__ dinv,
                             int* __restrict__ woff, int2* __restrict__ csr, int E) {
    int e = blockIdx.x * blockDim.x + threadIdx.x;
    if (e >= E) return;
    int s = src[e], d = dst[e];
    float nr = dinv[s] * w[e] * dinv[d];
    int pos = atomicAdd(&woff[d], 1);
    csr[pos] = make_int2(s, __float_as_int(nr));
}

// ---------------- pooling segment boundaries (pb is sorted ascending) ----------------
__global__ void seg_bounds_kernel(const int* __restrict__ pb, int* __restrict__ segstart, int N) {
    int s = blockIdx.x * blockDim.x + threadIdx.x;
    if (s > 256) return;
    // lower_bound: first index with pb[i] >= s
    int lo = 0, hi = N;
    while (lo < hi) {
        int mid = (lo + hi) >> 1;
        if (pb[mid] < s) lo = mid + 1; else hi = mid;
    }
    segstart[s] = lo;
}

// ---------------- weight split: W = Whi + Wlo (one launch for all 3 layers) ----------------
__global__ void wsplit_kernel(const float* __restrict__ W1, const float* __restrict__ W2,
                              const float* __restrict__ W3, float* __restrict__ hi,
                              float* __restrict__ lo) {
    int i = blockIdx.x * blockDim.x + threadIdx.x;
    if (i >= 45056) return;
    float w;
    if (i < 4096)       w = W1[i];
    else if (i < 12288) w = W2[i - 4096];
    else                w = W3[i - 12288];
    float h = __uint_as_float(f32_to_tf32(w));
    hi[i] = h;
    lo[i] = w - h;
}

// ---------------- CSR gather aggregation on INPUT features ----------------
// y[i] = dinv_i^2 * x[i] + sum_e norm_e * x[src_e]
template<int IN>
__global__ void gather_kernel(const int* __restrict__ rowptr, const int2* __restrict__ csr,
                              const float* __restrict__ X, const float* __restrict__ dinv,
                              float* __restrict__ Y, int N) {
    const int G = IN / 4;                 // threads per node
    const int NPB = 256 / G;              // nodes per block
    int lane = threadIdx.x % G;
    int node = blockIdx.x * NPB + threadIdx.x / G;
    if (node >= N) return;

    int beg = rowptr[node];
    int end = rowptr[node + 1];
    float di = dinv[node];
    float sl = di * di;

    float4 x = *reinterpret_cast<const float4*>(&X[(size_t)node * IN + lane * 4]);
    float4 acc = make_float4(sl * x.x, sl * x.y, sl * x.z, sl * x.w);

    int k = beg;
    for (; k + 4 <= end; k += 4) {
        int2 p0 = csr[k], p1 = csr[k + 1], p2 = csr[k + 2], p3 = csr[k + 3];
        float4 h0 = *reinterpret_cast<const float4*>(&X[(size_t)p0.x * IN + lane * 4]);
        float4 h1 = *reinterpret_cast<const float4*>(&X[(size_t)p1.x * IN + lane * 4]);
        float4 h2 = *reinterpret_cast<const float4*>(&X[(size_t)p2.x * IN + lane * 4]);
        float4 h3 = *reinterpret_cast<const float4*>(&X[(size_t)p3.x * IN + lane * 4]);
        float n0 = __int_as_float(p0.y), n1 = __int_as_float(p1.y);
        float n2 = __int_as_float(p2.y), n3 = __int_as_float(p3.y);
        acc.x += n0 * h0.x + n1 * h1.x + n2 * h2.x + n3 * h3.x;
        acc.y += n0 * h0.y + n1 * h1.y + n2 * h2.y + n3 * h3.y;
        acc.z += n0 * h0.z + n1 * h1.z + n2 * h2.z + n3 * h3.z;
        acc.w += n0 * h0.w + n1 * h1.w + n2 * h2.w + n3 * h3.w;
    }
    for (; k < end; k++) {
        int2 p0 = csr[k];
        float n0 = __int_as_float(p0.y);
        float4 h0 = *reinterpret_cast<const float4*>(&X[(size_t)p0.x * IN + lane * 4]);
        acc.x += n0 * h0.x; acc.y += n0 * h0.y;
        acc.z += n0 * h0.z; acc.w += n0 * h0.w;
    }
    *reinterpret_cast<float4*>(&Y[(size_t)node * IN + lane * 4]) = acc;
}

// ---------------- tf32 tensor-core GEMM: H = relu(A @ (Whi + Wlo) + bias) ----------------
template<int OUT, int K>
__global__ void __launch_bounds__(256) tf32_gemm_kernel(
    const float* __restrict__ A, const float* __restrict__ Bhi, const float* __restrict__ Blo,
    const float* __restrict__ bias, float* __restrict__ C, int N)
{
    __shared__ float As[32][136];
    __shared__ float Bh[32][72];
    __shared__ float Bl[32][72];

    int t = threadIdx.x;
    int lane = t & 31, w = t >> 5;
    int warpM = w & 3, warpN = w >> 2;
    int rowBase = blockIdx.x * 128;
    int colBase = blockIdx.y * 64;

    float acc[2][4][4];
    #pragma unroll
    for (int a = 0; a < 2; a++)
        #pragma unroll
        for (int b = 0; b < 4; b++)
            #pragma unroll
            for (int c = 0; c < 4; c++) acc[a][b][c] = 0.0f;

    for (int kb = 0; kb < K; kb += 32) {
        #pragma unroll
        for (int i = 0; i < 4; i++) {
            int lin = t + i * 256;
            int m = lin & 127, ks = lin >> 7;
            int r = rowBase + m;
            float4 v = make_float4(0.f, 0.f, 0.f, 0.f);
            if (r < N) v = *reinterpret_cast<const float4*>(&A[(size_t)r * K + kb + ks * 4]);
            As[ks * 4 + 0][m] = __uint_as_float(f32_to_tf32(v.x));
            As[ks * 4 + 1][m] = __uint_as_float(f32_to_tf32(v.y));
            As[ks * 4 + 2][m] = __uint_as_float(f32_to_tf32(v.z));
            As[ks * 4 + 3][m] = __uint_as_float(f32_to_tf32(v.w));
        }
        #pragma unroll
        for (int i = 0; i < 2; i++) {
            int lin = t + i * 256;
            int k = lin >> 4, n4 = (lin & 15) * 4;
            size_t off = (size_t)(kb + k) * OUT + colBase + n4;
            *reinterpret_cast<float4*>(&Bh[k][n4]) = *reinterpret_cast<const float4*>(&Bhi[off]);
            *reinterpret_cast<float4*>(&Bl[k][n4]) = *reinterpret_cast<const float4*>(&Blo[off]);
        }
        __syncthreads();

        #pragma unroll
        for (int kk = 0; kk < 32; kk += 8) {
            int kr = kk + (lane & 3);
            uint32_t af[2][4];
            #pragma unroll
            for (int mt = 0; mt < 2; mt++) {
                int m0 = warpM * 32 + mt * 16 + (lane >> 2);
                af[mt][0] = __float_as_uint(As[kr][m0]);
                af[mt][1] = __float_as_uint(As[kr][m0 + 8]);
                af[mt][2] = __float_as_uint(As[kr + 4][m0]);
                af[mt][3] = __float_as_uint(As[kr + 4][m0 + 8]);
            }
            #pragma unroll
            for (int nt = 0; nt < 4; nt++) {
                int n0 = warpN * 32 + nt * 8 + (lane >> 2);
                uint32_t bh0 = __float_as_uint(Bh[kr][n0]);
                uint32_t bh1 = __float_as_uint(Bh[kr + 4][n0]);
                uint32_t bl0 = __float_as_uint(Bl[kr][n0]);
                uint32_t bl1 = __float_as_uint(Bl[kr + 4][n0]);
                #pragma unroll
                for (int mt = 0; mt < 2; mt++) {
                    float* c = acc[mt][nt];
                    asm volatile(
                        "mma.sync.aligned.m16n8k8.row.col.f32.tf32.tf32.f32 "
                        "{%0,%1,%2,%3}, {%4,%5,%6,%7}, {%8,%9}, {%0,%1,%2,%3};"
                        : "+f"(c[0]), "+f"(c[1]), "+f"(c[2]), "+f"(c[3])
                        : "r"(af[mt][0]), "r"(af[mt][1]), "r"(af[mt][2]), "r"(af[mt][3]),
                          "r"(bh0), "r"(bh1));
                    asm volatile(
                        "mma.sync.aligned.m16n8k8.row.col.f32.tf32.tf32.f32 "
                        "{%0,%1,%2,%3}, {%4,%5,%6,%7}, {%8,%9}, {%0,%1,%2,%3};"
                        : "+f"(c[0]), "+f"(c[1]), "+f"(c[2]), "+f"(c[3])
                        : "r"(af[mt][0]), "r"(af[mt][1]), "r"(af[mt][2]), "r"(af[mt][3]),
                          "r"(bl0), "r"(bl1));
                }
            }
        }
        __syncthreads();
    }

    #pragma unroll
    for (int mt = 0; mt < 2; mt++) {
        #pragma unroll
        for (int nt = 0; nt < 4; nt++) {
            int row = rowBase + warpM * 32 + mt * 16 + (lane >> 2);
            int col = colBase + warpN * 32 + nt * 8 + 2 * (lane & 3);
            float b0 = bias[col], b1 = bias[col + 1];
            float* c = acc[mt][nt];
            if (row < N) {
                float2 o = make_float2(fmaxf(c[0] + b0, 0.f), fmaxf(c[1] + b1, 0.f));
                *reinterpret_cast<float2*>(&C[(size_t)row * OUT + col]) = o;
            }
            if (row + 8 < N) {
                float2 o = make_float2(fmaxf(c[2] + b0, 0.f), fmaxf(c[3] + b1, 0.f));
                *reinterpret_cast<float2*>(&C[(size_t)(row + 8) * OUT + col]) = o;
            }
        }
    }
}

// ---------------- pooling: per-(segment, slab) streaming sums, no atomics ----------------
// grid (256 segments, 4 slabs), 240 threads = 80 float4-cols x 3 node-ways
__global__ void pool_kernel(const float* __restrict__ conv3, const float* __restrict__ feat,
                            const int* __restrict__ segstart, float* __restrict__ pool) {
    __shared__ float4 sh[3][80];
    int seg = blockIdx.x, slab = blockIdx.y;
    int c = threadIdx.x % 80;
    int r = threadIdx.x / 80;            // 0..2
    int beg = segstart[seg], end = segstart[seg + 1];

    float4 acc = make_float4(0.f, 0.f, 0.f, 0.f);
    for (int i = beg + slab * 3 + r; i < end; i += 12) {
        float4 v;
        if (c < 64) v = *reinterpret_cast<const float4*>(&conv3[(size_t)i * 256 + c * 4]);
        else        v = *reinterpret_cast<const float4*>(&feat[(size_t)i * 64 + (c - 64) * 4]);
        acc.x += v.x; acc.y += v.y; acc.z += v.z; acc.w += v.w;
    }
    sh[r][c] = acc;
    __syncthreads();
    if (r == 0) {
        float4 a = sh[0][c], b = sh[1][c], d = sh[2][c];
        float4 o = make_float4(a.x + b.x + d.x, a.y + b.y + d.y,
                               a.z + b.z + d.z, a.w + b.w + d.w);
        *reinterpret_cast<float4*>(&pool[((size_t)slab * 256 + seg) * 320 + c * 4]) = o;
    }
}

// ---------------- MLP head ----------------
// fc1: grid (4 col-groups, 32 row-groups); each block does 8 rows x 256 cols
__global__ void fc1_kernel(const float* __restrict__ pool, const int* __restrict__ segstart,
                           const float* __restrict__ Wf1, const float* __restrict__ bf1,
                           float* __restrict__ fc1) {
    __shared__ float srow[8][320];
    __shared__ float sinv[8];
    int rowBase = blockIdx.y * 8;
    int col = blockIdx.x * 256 + threadIdx.x;

    for (int lin = threadIdx.x; lin < 8 * 320; lin += 256) {
        int rr = lin / 320, k = lin % 320;
        int row = rowBase + rr;
        float s = pool[((size_t)0 * 256 + row) * 320 + k]
                + pool[((size_t)1 * 256 + row) * 320 + k]
                + pool[((size_t)2 * 256 + row) * 320 + k]
                + pool[((size_t)3 * 256 + row) * 320 + k];
        srow[rr][k] = s;
    }
    if (threadIdx.x < 8) {
        int row = rowBase + threadIdx.x;
        int c = segstart[row + 1] - segstart[row];
        sinv[threadIdx.x] = 1.0f / fmaxf((float)c, 1.0f);
    }
    __syncthreads();

    float acc[8] = {};
    #pragma unroll 4
    for (int k = 0; k < 320; k++) {
        float wv = Wf1[(size_t)k * 1024 + col];
        #pragma unroll
        for (int rr = 0; rr < 8; rr++) acc[rr] += srow[rr][k] * wv;
    }
    float b = bf1[col];
    #pragma unroll
    for (int rr = 0; rr < 8; rr++) {
        float v = acc[rr] * sinv[rr] + b;
        fc1[(size_t)(rowBase + rr) * 1024 + col] = fmaxf(v, 0.f);
    }
}

__global__ void fc2_kernel(const float* __restrict__ fc1, const float* __restrict__ Wf2,
                           const float* __restrict__ bf2, float* __restrict__ out) {
    int row = blockIdx.x;
    float a = 0.f;
    for (int j = threadIdx.x; j < 1024; j += 256)
        a += fc1[(size_t)row * 1024 + j] * Wf2[j];
    __shared__ float red[256];
    red[threadIdx.x] = a;
    __syncthreads();
    for (int s = 128; s > 0; s >>= 1) {
        if (threadIdx.x < s) red[threadIdx.x] += red[threadIdx.x + s];
        __syncthreads();
    }
    if (threadIdx.x == 0) out[row] = red[0] + bf2[0];
}

// ---------------- launch ----------------
extern "C" void kernel_launch(void* const* d_in, const int* in_sizes, int n_in,
                              void* d_out, int out_size) {
    const float* feature = (const float*)d_in[0];
    const int*   ei      = (const int*)d_in[1];
    const float* weight  = (const float*)d_in[2];
    const int*   pb      = (const int*)d_in[3];
    const float* W1 = (const float*)d_in[4];  const float* b1  = (const float*)d_in[5];
    const float* W2 = (const float*)d_in[6];  const float* b2  = (const float*)d_in[7];
    const float* W3 = (const float*)d_in[8];  const float* b3  = (const float*)d_in[9];
    const float* Wf1 = (const float*)d_in[10]; const float* bf1 = (const float*)d_in[11];
    const float* Wf2 = (const float*)d_in[12]; const float* bf2 = (const float*)d_in[13];
    float* out = (float*)d_out;

    int N = in_sizes[0] / 64;
    int E = in_sizes[2];
    const int* src = ei;
    const int* dst = ei + E;

    float *bufH, *bufY, *dinv, *pool, *fc1, *whi, *wlo;
    int *rowptr, *woff, *hist, *bsums, *segstart;
    int2 *csr;
    cudaGetSymbolAddress((void**)&bufH, g_bufH);
    cudaGetSymbolAddress((void**)&bufY, g_bufY);
    cudaGetSymbolAddress((void**)&dinv, g_dinv);
    cudaGetSymbolAddress((void**)&rowptr, g_rowptr);
    cudaGetSymbolAddress((void**)&woff, g_woff);
    cudaGetSymbolAddress((void**)&hist, g_hist);
    cudaGetSymbolAddress((void**)&bsums, g_bsums);
    cudaGetSymbolAddress((void**)&csr, g_csr);
    cudaGetSymbolAddress((void**)&segstart, g_segstart);
    cudaGetSymbolAddress((void**)&whi, g_whi);
    cudaGetSymbolAddress((void**)&wlo, g_wlo);
    cudaGetSymbolAddress((void**)&pool, g_pool);
    cudaGetSymbolAddress((void**)&fc1,  g_fc1);

    const int T = 256;
    int nb = (N + 1023) / 1024;

    wsplit_kernel<<<(45056 + T - 1) / T, T>>>(W1, W2, W3, whi, wlo);
    seg_bounds_kernel<<<2, 160>>>(pb, segstart, N);

    // degrees + histogram
    deg_init_kernel<<<(N + T - 1) / T, T>>>(dinv, hist, N);
    deg_acc_kernel<<<(E + T - 1) / T, T>>>(dst, weight, dinv, hist, E);

    // CSR build (dinv computed inside scan_block)
    scan_block_kernel<<<nb, 1024>>>(hist, rowptr, bsums, dinv, N);
    scan_sums_kernel<<<1, 128>>>(bsums, nb);
    add_off_kernel<<<(N + 1 + T - 1) / T, T>>>(rowptr, bsums, woff, N, E);
    place_kernel<<<(E + T - 1) / T, T>>>(src, dst, weight, dinv, woff, csr, E);

    int gb128 = (N + 127) / 128;

    // layer 1: y1 = agg(feature) [N,64]; h1 = relu(y1@W1 + b1) [N,64]
    gather_kernel<64><<<(N * 16 + 255) / 256, 256>>>(rowptr, csr, feature, dinv, bufY, N);
    tf32_gemm_kernel<64, 64><<<dim3(gb128, 1), 256>>>(bufY, whi, wlo, b1, bufH, N);

    // layer 2
    gather_kernel<64><<<(N * 16 + 255) / 256, 256>>>(rowptr, csr, bufH, dinv, bufY, N);
    tf32_gemm_kernel<128, 64><<<dim3(gb128, 2), 256>>>(bufY, whi + 4096, wlo + 4096, b2, bufH, N);

    // layer 3
    gather_kernel<128><<<(N * 32 + 255) / 256, 256>>>(rowptr, csr, bufH, dinv, bufY, N);
    tf32_gemm_kernel<256, 128><<<dim3(gb128, 4), 256>>>(bufY, whi + 12288, wlo + 12288, b3, bufH, N);

    // pooling + MLP head
    pool_kernel<<<dim3(256, 4), 240>>>(bufH, feature, segstart, pool);
    fc1_kernel<<<dim3(4, 32), 256>>>(pool, segstart, Wf1, bf1, fc1);
    fc2_kernel<<<256, 256>>>(fc1, Wf2, bf2, out);
}

// round 11
// speedup vs baseline: 3.2671x; 1.3546x over previous
#include <cuda_runtime.h>
#include <cuda_bf16.h>
#include <cstdint>

// ---------------- static scratch (no runtime allocation allowed) ----------------
#define MAXN 100000
#define MAXE 1200000

__device__ float          g_bufH[(size_t)MAXN * 256];   // layer-3 output (fp32, feeds pool)
__device__ __nv_bfloat16  g_bufHb[(size_t)MAXN * 128];  // layer-1/2 outputs (bf16)
__device__ __nv_bfloat16  g_bufY[(size_t)MAXN * 128];   // aggregated features (bf16)
__device__ __nv_bfloat16  g_featb[(size_t)MAXN * 64];   // bf16 copy of input features
__device__ float2 g_dc[MAXN];                  // (weighted degree, count)
__device__ float  g_dinv[MAXN];                // d^{-1/2}
__device__ int    g_rowptr[MAXN + 1];
__device__ int    g_woff[MAXN + 1];
__device__ int    g_bsums[128];
__device__ int2   g_csr[MAXE];                 // packed (src, norm)
__device__ int    g_segstart[257];
__device__ __nv_bfloat16 g_whiT[45056];        // bf16-hi of W1|W2|W3, TRANSPOSED [OUT][K]
__device__ __nv_bfloat16 g_wloT[45056];        // bf16 residual, transposed
__device__ float g_pool[4 * 256 * 320];
__device__ float g_fc1[256 * 1024];

// ---------------- helpers ----------------
__device__ __forceinline__ void bf8_to_f8(uint4 v, float* f) {
    const __nv_bfloat162* p = reinterpret_cast<const __nv_bfloat162*>(&v);
    #pragma unroll
    for (int j = 0; j < 4; j++) {
        float2 t = __bfloat1622float2(p[j]);
        f[2 * j] = t.x; f[2 * j + 1] = t.y;
    }
}

// ---------------- prep: degree (float2 atomic) ----------------
__global__ void deg_init_kernel(float2* dc, int N) {
    int i = blockIdx.x * blockDim.x + threadIdx.x;
    if (i < N) dc[i] = make_float2(1.0f, 0.0f);   // self-loop weight
}

__global__ void deg_acc_kernel(const int* __restrict__ dst, const float* __restrict__ w,
                               float2* __restrict__ dc, int E) {
    int e = blockIdx.x * blockDim.x + threadIdx.x;
    if (e < E) atomicAdd(&dc[dst[e]], make_float2(w[e], 1.0f));
}

// ---------------- scan: cnt -> rowptr (exclusive); dinv folded in ----------------
__global__ void scan_block_kernel(const float2* __restrict__ dc, int* __restrict__ rowptr,
                                  int* __restrict__ bsums, float* __restrict__ dinv, int N) {
    __shared__ int sh[1024];
    int i = blockIdx.x * 1024 + threadIdx.x;
    int v = 0;
    if (i < N) {
        float2 d = dc[i];
        v = (int)(d.y + 0.5f);
        dinv[i] = rsqrtf(d.x);            // deg >= 1 (self-loop)
    }
    sh[threadIdx.x] = v;
    __syncthreads();
    for (int off = 1; off < 1024; off <<= 1) {
        int t = (threadIdx.x >= off) ? sh[threadIdx.x - off] : 0;
        __syncthreads();
        sh[threadIdx.x] += t;
        __syncthreads();
    }
    if (i < N) rowptr[i] = sh[threadIdx.x] - v;
    if (threadIdx.x == 1023) bsums[blockIdx.x] = sh[1023];
}

__global__ void scan_sums_kernel(int* bsums, int nb) {
    __shared__ int sh[128];
    int v = (threadIdx.x < nb) ? bsums[threadIdx.x] : 0;
    sh[threadIdx.x] = v;
    __syncthreads();
    for (int off = 1; off < 128; off <<= 1) {
        int t = (threadIdx.x >= off) ? sh[threadIdx.x - off] : 0;
        __syncthreads();
        sh[threadIdx.x] += t;
        __syncthreads();
    }
    if (threadIdx.x < nb) bsums[threadIdx.x] = sh[threadIdx.x] - v;
}

__global__ void add_off_kernel(int* __restrict__ rowptr, const int* __restrict__ bsums,
                               int* __restrict__ woff, int N, int E) {
    int i = blockIdx.x * blockDim.x + threadIdx.x;
    if (i < N) {
        int r = rowptr[i] + bsums[i >> 10];
        rowptr[i] = r;
        woff[i] = r;
    }
    if (i == N) rowptr[N] = E;
}

__global__ void place_kernel(const int* __restrict__ src, const int* __restrict__ dst,
                             const float* __restrict__ w, const float* __restrict__ dinv,
                             int* __restrict__ woff, int2* __restrict__ csr, int E) {
    int e = blockIdx.x * blockDim.x + threadIdx.x;
    if (e >= E) return;
    int s = src[e], d = dst[e];
    float nr = dinv[s] * w[e] * dinv[d];
    int pos = atomicAdd(&woff[d], 1);
    csr[pos] = make_int2(s, __float_as_int(nr));
}

__global__ void seg_bounds_kernel(const int* __restrict__ pb, int* __restrict__ segstart, int N) {
    int s = blockIdx.x * blockDim.x + threadIdx.x;
    if (s > 256) return;
    int lo = 0, hi = N;
    while (lo < hi) {
        int mid = (lo + hi) >> 1;
        if (pb[mid] < s) lo = mid + 1; else hi = mid;
    }
    segstart[s] = lo;
}

// ---------------- weight split+transpose: W[k][n] -> WT[n][k], bf16 hi/lo ----------------
__global__ void wsplit_kernel(const float* __restrict__ W1, const float* __restrict__ W2,
                              const float* __restrict__ W3, __nv_bfloat16* __restrict__ hi,
                              __nv_bfloat16* __restrict__ lo) {
    int i = blockIdx.x * blockDim.x + threadIdx.x;
    if (i >= 45056) return;
    float w; int o;
    if (i < 4096)       { int k = i >> 6, n = i & 63;  w = W1[i];          o = n * 64 + k; }
    else if (i < 12288) { int j = i - 4096;  int k = j >> 7, n = j & 127; w = W2[j]; o = 4096  + n * 64  + k; }
    else                { int j = i - 12288; int k = j >> 8, n = j & 255; w = W3[j]; o = 12288 + n * 128 + k; }
    __nv_bfloat16 h = __float2bfloat16(w);
    hi[o] = h;
    lo[o] = __float2bfloat16(w - __bfloat162float(h));
}

// ---------------- feature -> bf16 ----------------
__global__ void featcvt_kernel(const float* __restrict__ f, __nv_bfloat16* __restrict__ fb, int n4) {
    int i = blockIdx.x * blockDim.x + threadIdx.x;
    if (i >= n4) return;
    float4 v = reinterpret_cast<const float4*>(f)[i];
    __nv_bfloat162* o = reinterpret_cast<__nv_bfloat162*>(fb) + i * 2;
    o[0] = __floats2bfloat162_rn(v.x, v.y);
    o[1] = __floats2bfloat162_rn(v.z, v.w);
}

// ---------------- CSR gather aggregation (bf16 in/out, fp32 accumulate) ----------------
// y[i] = dinv_i^2 * x[i] + sum_e norm_e * x[src_e]
template<int IN>
__global__ void gather_kernel(const int* __restrict__ rowptr, const int2* __restrict__ csr,
                              const __nv_bfloat16* __restrict__ X, const float* __restrict__ dinv,
                              __nv_bfloat16* __restrict__ Y, int N) {
    const int G = IN / 8;                 // threads per node (8 bf16 = 16B each)
    const int NPB = 256 / G;
    int lane = threadIdx.x % G;
    int node = blockIdx.x * NPB + threadIdx.x / G;
    if (node >= N) return;

    int beg = rowptr[node];
    int end = rowptr[node + 1];
    float di = dinv[node];
    float sl = di * di;

    float acc[8];
    {
        uint4 xv = *reinterpret_cast<const uint4*>(&X[(size_t)node * IN + lane * 8]);
        float xf[8]; bf8_to_f8(xv, xf);
        #pragma unroll
        for (int j = 0; j < 8; j++) acc[j] = sl * xf[j];
    }

    int k = beg;
    for (; k + 4 <= end; k += 4) {
        int2 p0 = csr[k], p1 = csr[k + 1], p2 = csr[k + 2], p3 = csr[k + 3];
        uint4 v0 = *reinterpret_cast<const uint4*>(&X[(size_t)p0.x * IN + lane * 8]);
        uint4 v1 = *reinterpret_cast<const uint4*>(&X[(size_t)p1.x * IN + lane * 8]);
        uint4 v2 = *reinterpret_cast<const uint4*>(&X[(size_t)p2.x * IN + lane * 8]);
        uint4 v3 = *reinterpret_cast<const uint4*>(&X[(size_t)p3.x * IN + lane * 8]);
        float n0 = __int_as_float(p0.y), n1 = __int_as_float(p1.y);
        float n2 = __int_as_float(p2.y), n3 = __int_as_float(p3.y);
        float f0[8], f1[8], f2[8], f3[8];
        bf8_to_f8(v0, f0); bf8_to_f8(v1, f1); bf8_to_f8(v2, f2); bf8_to_f8(v3, f3);
        #pragma unroll
        for (int j = 0; j < 8; j++)
            acc[j] += n0 * f0[j] + n1 * f1[j] + n2 * f2[j] + n3 * f3[j];
    }
    for (; k < end; k++) {
        int2 p0 = csr[k];
        float n0 = __int_as_float(p0.y);
        uint4 v0 = *reinterpret_cast<const uint4*>(&X[(size_t)p0.x * IN + lane * 8]);
        float f0[8]; bf8_to_f8(v0, f0);
        #pragma unroll
        for (int j = 0; j < 8; j++) acc[j] += n0 * f0[j];
    }

    uint4 o;
    __nv_bfloat162* q = reinterpret_cast<__nv_bfloat162*>(&o);
    #pragma unroll
    for (int j = 0; j < 4; j++) q[j] = __floats2bfloat162_rn(acc[2 * j], acc[2 * j + 1]);
    *reinterpret_cast<uint4*>(&Y[(size_t)node * IN + lane * 8]) = o;
}

// ---------------- bf16 tensor-core GEMM: H = relu(A @ (Whi + Wlo) + bias) ----------------
// BM=128, BN=64, BK=32; 8 warps (4M x 2N), warp tile 32x32, mma.m16n8k16.bf16 x2 (hi/lo).
// W tiles come pre-transposed [OUT][K] so SMEM is [n][k] (pairs contiguous in k).
template<int OUT, int K, bool OUT_BF16>
__global__ void __launch_bounds__(256) bf16_gemm_kernel(
    const __nv_bfloat16* __restrict__ A, const __nv_bfloat16* __restrict__ BhiT,
    const __nv_bfloat16* __restrict__ BloT, const float* __restrict__ bias,
    void* __restrict__ Cout, int N)
{
    __shared__ __align__(16) __nv_bfloat16 As[128][40];   // [m][k], stride 40 (20 words: conflict-free)
    __shared__ __align__(16) __nv_bfloat16 Bh[64][40];    // [n][k]
    __shared__ __align__(16) __nv_bfloat16 Bl[64][40];

    int t = threadIdx.x;
    int lane = t & 31, w = t >> 5;
    int warpM = w & 3, warpN = w >> 2;
    int g = lane >> 2, tc = lane & 3;
    int rowBase = blockIdx.x * 128;
    int colBase = blockIdx.y * 64;

    float acc[2][4][4];
    #pragma unroll
    for (int a = 0; a < 2; a++)
        #pragma unroll
        for (int b = 0; b < 4; b++)
            #pragma unroll
            for (int c = 0; c < 4; c++) acc[a][b][c] = 0.0f;

    for (int kb = 0; kb < K; kb += 32) {
        // A tile: 128m x 32k bf16, uint4 = 8 bf16 per thread x2
        #pragma unroll
        for (int i = 0; i < 2; i++) {
            int lin = t + i * 256;
            int m = lin >> 2, kq = (lin & 3) * 8;
            uint4 v = make_uint4(0u, 0u, 0u, 0u);
            if (rowBase + m < N)
                v = *reinterpret_cast<const uint4*>(&A[(size_t)(rowBase + m) * K + kb + kq]);
            *reinterpret_cast<uint4*>(&As[m][kq]) = v;
        }
        // B tiles: 64n x 32k each (hi, lo), coalesced from transposed weights
        {
            int n = t >> 2, kq = (t & 3) * 8;
            size_t off = (size_t)(colBase + n) * K + kb + kq;
            *reinterpret_cast<uint4*>(&Bh[n][kq]) = *reinterpret_cast<const uint4*>(&BhiT[off]);
            *reinterpret_cast<uint4*>(&Bl[n][kq]) = *reinterpret_cast<const uint4*>(&BloT[off]);
        }
        __syncthreads();

        #pragma unroll
        for (int ks = 0; ks < 32; ks += 16) {
            uint32_t af[2][4];
            #pragma unroll
            for (int mt = 0; mt < 2; mt++) {
                int m0 = warpM * 32 + mt * 16 + g;
                af[mt][0] = *reinterpret_cast<const uint32_t*>(&As[m0][ks + tc * 2]);
                af[mt][1] = *reinterpret_cast<const uint32_t*>(&As[m0 + 8][ks + tc * 2]);
                af[mt][2] = *reinterpret_cast<const uint32_t*>(&As[m0][ks + tc * 2 + 8]);
                af[mt][3] = *reinterpret_cast<const uint32_t*>(&As[m0 + 8][ks + tc * 2 + 8]);
            }
            #pragma unroll
            for (int nt = 0; nt < 4; nt++) {
                int n0 = warpN * 32 + nt * 8 + g;
                uint32_t bh0 = *reinterpret_cast<const uint32_t*>(&Bh[n0][ks + tc * 2]);
                uint32_t bh1 = *reinterpret_cast<const uint32_t*>(&Bh[n0][ks + tc * 2 + 8]);
                uint32_t bl0 = *reinterpret_cast<const uint32_t*>(&Bl[n0][ks + tc * 2]);
                uint32_t bl1 = *reinterpret_cast<const uint32_t*>(&Bl[n0][ks + tc * 2 + 8]);
                #pragma unroll
                for (int mt = 0; mt < 2; mt++) {
                    float* c = acc[mt][nt];
                    asm volatile(
                        "mma.sync.aligned.m16n8k16.row.col.f32.bf16.bf16.f32 "
                        "{%0,%1,%2,%3}, {%4,%5,%6,%7}, {%8,%9}, {%0,%1,%2,%3};"
                        : "+f"(c[0]), "+f"(c[1]), "+f"(c[2]), "+f"(c[3])
                        : "r"(af[mt][0]), "r"(af[mt][1]), "r"(af[mt][2]), "r"(af[mt][3]),
                          "r"(bh0), "r"(bh1));
                    asm volatile(
                        "mma.sync.aligned.m16n8k16.row.col.f32.bf16.bf16.f32 "
                        "{%0,%1,%2,%3}, {%4,%5,%6,%7}, {%8,%9}, {%0,%1,%2,%3};"
                        : "+f"(c[0]), "+f"(c[1]), "+f"(c[2]), "+f"(c[3])
                        : "r"(af[mt][0]), "r"(af[mt][1]), "r"(af[mt][2]), "r"(af[mt][3]),
                          "r"(bl0), "r"(bl1));
                }
            }
        }
        __syncthreads();
    }

    // epilogue: bias + relu
    #pragma unroll
    for (int mt = 0; mt < 2; mt++) {
        #pragma unroll
        for (int nt = 0; nt < 4; nt++) {
            int row = rowBase + warpM * 32 + mt * 16 + g;
            int col = colBase + warpN * 32 + nt * 8 + tc * 2;
            float b0 = bias[col], b1 = bias[col + 1];
            float* c = acc[mt][nt];
            float v00 = fmaxf(c[0] + b0, 0.f), v01 = fmaxf(c[1] + b1, 0.f);
            float v10 = fmaxf(c[2] + b0, 0.f), v11 = fmaxf(c[3] + b1, 0.f);
            if (OUT_BF16) {
                __nv_bfloat16* Cb = (__nv_bfloat16*)Cout;
                if (row < N)
                    *reinterpret_cast<__nv_bfloat162*>(&Cb[(size_t)row * OUT + col]) =
                        __floats2bfloat162_rn(v00, v01);
                if (row + 8 < N)
                    *reinterpret_cast<__nv_bfloat162*>(&Cb[(size_t)(row + 8) * OUT + col]) =
                        __floats2bfloat162_rn(v10, v11);
            } else {
                float* Cf = (float*)Cout;
                if (row < N)
                    *reinterpret_cast<float2*>(&Cf[(size_t)row * OUT + col]) = make_float2(v00, v01);
                if (row + 8 < N)
                    *reinterpret_cast<float2*>(&Cf[(size_t)(row + 8) * OUT + col]) = make_float2(v10, v11);
            }
        }
    }
}

// ---------------- pooling: per-(segment, slab) streaming sums, no atomics ----------------
__global__ void pool_kernel(const float* __restrict__ conv3, const float* __restrict__ feat,
                            const int* __restrict__ segstart, float* __restrict__ pool) {
    __shared__ float4 sh[3][80];
    int seg = blockIdx.x, slab = blockIdx.y;
    int c = threadIdx.x % 80;
    int r = threadIdx.x / 80;
    int beg = segstart[seg], end = segstart[seg + 1];

    float4 acc = make_float4(0.f, 0.f, 0.f, 0.f);
    for (int i = beg + slab * 3 + r; i < end; i += 12) {
        float4 v;
        if (c < 64) v = *reinterpret_cast<const float4*>(&conv3[(size_t)i * 256 + c * 4]);
        else        v = *reinterpret_cast<const float4*>(&feat[(size_t)i * 64 + (c - 64) * 4]);
        acc.x += v.x; acc.y += v.y; acc.z += v.z; acc.w += v.w;
    }
    sh[r][c] = acc;
    __syncthreads();
    if (r == 0) {
        float4 a = sh[0][c], b = sh[1][c], d = sh[2][c];
        float4 o = make_float4(a.x + b.x + d.x, a.y + b.y + d.y,
                               a.z + b.z + d.z, a.w + b.w + d.w);
        *reinterpret_cast<float4*>(&pool[((size_t)slab * 256 + seg) * 320 + c * 4]) = o;
    }
}

// ---------------- MLP head ----------------
__global__ void fc1_kernel(const float* __restrict__ pool, const int* __restrict__ segstart,
                           const float* __restrict__ Wf1, const float* __restrict__ bf1,
                           float* __restrict__ fc1) {
    __shared__ float srow[8][320];
    __shared__ float sinv[8];
    int rowBase = blockIdx.y * 8;
    int col = blockIdx.x * 256 + threadIdx.x;

    for (int lin = threadIdx.x; lin < 8 * 320; lin += 256) {
        int rr = lin / 320, k = lin % 320;
        int row = rowBase + rr;
        float s = pool[((size_t)0 * 256 + row) * 320 + k]
                + pool[((size_t)1 * 256 + row) * 320 + k]
                + pool[((size_t)2 * 256 + row) * 320 + k]
                + pool[((size_t)3 * 256 + row) * 320 + k];
        srow[rr][k] = s;
    }
    if (threadIdx.x < 8) {
        int row = rowBase + threadIdx.x;
        int c = segstart[row + 1] - segstart[row];
        sinv[threadIdx.x] = 1.0f / fmaxf((float)c, 1.0f);
    }
    __syncthreads();

    float acc[8] = {};
    #pragma unroll 4
    for (int k = 0; k < 320; k++) {
        float wv = Wf1[(size_t)k * 1024 + col];
        #pragma unroll
        for (int rr = 0; rr < 8; rr++) acc[rr] += srow[rr][k] * wv;
    }
    float b = bf1[col];
    #pragma unroll
    for (int rr = 0; rr < 8; rr++) {
        float v = acc[rr] * sinv[rr] + b;
        fc1[(size_t)(rowBase + rr) * 1024 + col] = fmaxf(v, 0.f);
    }
}

__global__ void fc2_kernel(const float* __restrict__ fc1, const float* __restrict__ Wf2,
                           const float* __restrict__ bf2, float* __restrict__ out) {
    int row = blockIdx.x;
    float a = 0.f;
    for (int j = threadIdx.x; j < 1024; j += 256)
        a += fc1[(size_t)row * 1024 + j] * Wf2[j];
    __shared__ float red[256];
    red[threadIdx.x] = a;
    __syncthreads();
    for (int s = 128; s > 0; s >>= 1) {
        if (threadIdx.x < s) red[threadIdx.x] += red[threadIdx.x + s];
        __syncthreads();
    }
    if (threadIdx.x == 0) out[row] = red[0] + bf2[0];
}

// ---------------- launch ----------------
extern "C" void kernel_launch(void* const* d_in, const int* in_sizes, int n_in,
                              void* d_out, int out_size) {
    const float* feature = (const float*)d_in[0];
    const int*   ei      = (const int*)d_in[1];
    const float* weight  = (const float*)d_in[2];
    const int*   pb      = (const int*)d_in[3];
    const float* W1 = (const float*)d_in[4];  const float* b1  = (const float*)d_in[5];
    const float* W2 = (const float*)d_in[6];  const float* b2  = (const float*)d_in[7];
    const float* W3 = (const float*)d_in[8];  const float* b3  = (const float*)d_in[9];
    const float* Wf1 = (const float*)d_in[10]; const float* bf1 = (const float*)d_in[11];
    const float* Wf2 = (const float*)d_in[12]; const float* bf2 = (const float*)d_in[13];
    float* out = (float*)d_out;

    int N = in_sizes[0] / 64;
    int E = in_sizes[2];
    const int* src = ei;
    const int* dst = ei + E;

    float *bufH, *dinv, *pool, *fc1;
    __nv_bfloat16 *bufHb, *bufY, *featb, *whiT, *wloT;
    float2 *dc;
    int *rowptr, *woff, *bsums, *segstart;
    int2 *csr;
    cudaGetSymbolAddress((void**)&bufH, g_bufH);
    cudaGetSymbolAddress((void**)&bufHb, g_bufHb);
    cudaGetSymbolAddress((void**)&bufY, g_bufY);
    cudaGetSymbolAddress((void**)&featb, g_featb);
    cudaGetSymbolAddress((void**)&dc, g_dc);
    cudaGetSymbolAddress((void**)&dinv, g_dinv);
    cudaGetSymbolAddress((void**)&rowptr, g_rowptr);
    cudaGetSymbolAddress((void**)&woff, g_woff);
    cudaGetSymbolAddress((void**)&bsums, g_bsums);
    cudaGetSymbolAddress((void**)&csr, g_csr);
    cudaGetSymbolAddress((void**)&segstart, g_segstart);
    cudaGetSymbolAddress((void**)&whiT, g_whiT);
    cudaGetSymbolAddress((void**)&wloT, g_wloT);
    cudaGetSymbolAddress((void**)&pool, g_pool);
    cudaGetSymbolAddress((void**)&fc1,  g_fc1);

    const int T = 256;
    int nb = (N + 1023) / 1024;

    wsplit_kernel<<<(45056 + T - 1) / T, T>>>(W1, W2, W3, whiT, wloT);
    featcvt_kernel<<<(N * 16 + T - 1) / T, T>>>(feature, featb, N * 16);
    seg_bounds_kernel<<<2, 160>>>(pb, segstart, N);

    // degrees (vector atomic) + CSR build
    deg_init_kernel<<<(N + T - 1) / T, T>>>(dc, N);
    deg_acc_kernel<<<(E + T - 1) / T, T>>>(dst, weight, dc, E);
    scan_block_kernel<<<nb, 1024>>>(dc, rowptr, bsums, dinv, N);
    scan_sums_kernel<<<1, 128>>>(bsums, nb);
    add_off_kernel<<<(N + 1 + T - 1) / T, T>>>(rowptr, bsums, woff, N, E);
    place_kernel<<<(E + T - 1) / T, T>>>(src, dst, weight, dinv, woff, csr, E);

    int gb128 = (N + 127) / 128;

    // layer 1: y1 = agg(featb) [N,64] bf16; h1 = relu(y1@W1+b1) [N,64] bf16
    gather_kernel<64><<<(N * 8 + 255) / 256, 256>>>(rowptr, csr, featb, dinv, bufY, N);
    bf16_gemm_kernel<64, 64, true><<<dim3(gb128, 1), 256>>>(bufY, whiT, wloT, b1, bufHb, N);

    // layer 2: [N,64] -> [N,128] bf16
    gather_kernel<64><<<(N * 8 + 255) / 256, 256>>>(rowptr, csr, bufHb, dinv, bufY, N);
    bf16_gemm_kernel<128, 64, true><<<dim3(gb128, 2), 256>>>(bufY, whiT + 4096, wloT + 4096, b2, bufHb, N);

    // layer 3: [N,128] -> [N,256] fp32 (feeds pool)
    gather_kernel<128><<<(N * 16 + 255) / 256, 256>>>(rowptr, csr, bufHb, dinv, bufY, N);
    bf16_gemm_kernel<256, 128, false><<<dim3(gb128, 4), 256>>>(bufY, whiT + 12288, wloT + 12288, b3, bufH, N);

    // pooling + MLP head
    pool_kernel<<<dim3(256, 4), 240>>>(bufH, feature, segstart, pool);
    fc1_kernel<<<dim3(4, 32), 256>>>(pool, segstart, Wf1, bf1, fc1);
    fc2_kernel<<<256, 256>>>(fc1, Wf2, bf2, out);
}

// round 12
// speedup vs baseline: 3.4187x; 1.0464x over previous
#include <cuda_runtime.h>
#include <cuda_bf16.h>
#include <cstdint>

// ---------------- static scratch (no runtime allocation allowed) ----------------
#define MAXN 100000
#define MAXE 1200000

__device__ __nv_bfloat16  g_actb[(size_t)MAXN * 256];   // layer outputs h1(64)/h2(128)/h3(256), bf16
__device__ __nv_bfloat16  g_bufY[(size_t)MAXN * 128];   // aggregated features (bf16)
__device__ __nv_bfloat16  g_featb[(size_t)MAXN * 64];   // bf16 copy of input features
__device__ float2 g_dc[MAXN];                  // (weighted degree, count)
__device__ float  g_dinv[MAXN];                // d^{-1/2}
__device__ int    g_rowptr[MAXN + 1];
__device__ int    g_woff[MAXN + 1];
__device__ int    g_bsums[128];
__device__ int2   g_csr[MAXE];                 // packed (src, norm)
__device__ int    g_segstart[257];
__device__ __nv_bfloat16 g_whiT[45056];        // bf16-hi of W1|W2|W3, TRANSPOSED [OUT][K]
__device__ __nv_bfloat16 g_wloT[45056];        // bf16 residual, transposed
__device__ float g_pool[4 * 256 * 320];
__device__ float g_fc1[256 * 1024];

// ---------------- helpers ----------------
__device__ __forceinline__ void bf8_to_f8(uint4 v, float* f) {
    const __nv_bfloat162* p = reinterpret_cast<const __nv_bfloat162*>(&v);
    #pragma unroll
    for (int j = 0; j < 4; j++) {
        float2 t = __bfloat1622float2(p[j]);
        f[2 * j] = t.x; f[2 * j + 1] = t.y;
    }
}

__device__ __forceinline__ void cp_async16(void* smem, const void* gmem, int src_bytes) {
    uint32_t s = (uint32_t)__cvta_generic_to_shared(smem);
    asm volatile("cp.async.cg.shared.global [%0], [%1], 16, %2;" :: "r"(s), "l"(gmem), "r"(src_bytes));
}
#define CP_COMMIT asm volatile("cp.async.commit_group;")

// ---------------- fused prep: wsplit | featcvt | seg_bounds | deg_init ----------------
__global__ void prep_kernel(const float* __restrict__ W1, const float* __restrict__ W2,
                            const float* __restrict__ W3, __nv_bfloat16* __restrict__ hi,
                            __nv_bfloat16* __restrict__ lo,
                            const float* __restrict__ feature, __nv_bfloat16* __restrict__ featb,
                            const int* __restrict__ pb, int* __restrict__ segstart,
                            float2* __restrict__ dc, int N, int nWS, int nFC) {
    int b = blockIdx.x, t = threadIdx.x;
    if (b < nWS) {
        int i = b * 256 + t;
        if (i < 45056) {
            float w; int o;
            if (i < 4096)       { int k = i >> 6, n = i & 63;  w = W1[i];          o = n * 64 + k; }
            else if (i < 12288) { int j = i - 4096;  int k = j >> 7, n = j & 127; w = W2[j]; o = 4096  + n * 64  + k; }
            else                { int j = i - 12288; int k = j >> 8, n = j & 255; w = W3[j]; o = 12288 + n * 128 + k; }
            __nv_bfloat16 h = __float2bfloat16(w);
            hi[o] = h;
            lo[o] = __float2bfloat16(w - __bfloat162float(h));
        }
    } else if (b < nWS + nFC) {
        int i = (b - nWS) * 256 + t;
        if (i < N * 16) {
            float4 v = reinterpret_cast<const float4*>(feature)[i];
            __nv_bfloat162* o = reinterpret_cast<__nv_bfloat162*>(featb) + i * 2;
            o[0] = __floats2bfloat162_rn(v.x, v.y);
            o[1] = __floats2bfloat162_rn(v.z, v.w);
        }
    } else if (b < nWS + nFC + 2) {
        int s = (b - nWS - nFC) * 256 + t;
        if (s <= 256) {
            int lo2 = 0, hi2 = N;
            while (lo2 < hi2) {
                int mid = (lo2 + hi2) >> 1;
                if (pb[mid] < s) lo2 = mid + 1; else hi2 = mid;
            }
            segstart[s] = lo2;
        }
    } else {
        int i = (b - nWS - nFC - 2) * 256 + t;
        if (i < N) dc[i] = make_float2(1.0f, 0.0f);   // self-loop weight
    }
}

__global__ void deg_acc_kernel(const int* __restrict__ dst, const float* __restrict__ w,
                               float2* __restrict__ dc, int E) {
    int e = blockIdx.x * blockDim.x + threadIdx.x;
    if (e < E) atomicAdd(&dc[dst[e]], make_float2(w[e], 1.0f));
}

// ---------------- scan: cnt -> rowptr (exclusive); dinv folded in ----------------
__global__ void scan_block_kernel(const float2* __restrict__ dc, int* __restrict__ rowptr,
                                  int* __restrict__ bsums, float* __restrict__ dinv, int N) {
    __shared__ int sh[1024];
    int i = blockIdx.x * 1024 + threadIdx.x;
    int v = 0;
    if (i < N) {
        float2 d = dc[i];
        v = (int)(d.y + 0.5f);
        dinv[i] = rsqrtf(d.x);            // deg >= 1 (self-loop)
    }
    sh[threadIdx.x] = v;
    __syncthreads();
    for (int off = 1; off < 1024; off <<= 1) {
        int t = (threadIdx.x >= off) ? sh[threadIdx.x - off] : 0;
        __syncthreads();
        sh[threadIdx.x] += t;
        __syncthreads();
    }
    if (i < N) rowptr[i] = sh[threadIdx.x] - v;
    if (threadIdx.x == 1023) bsums[blockIdx.x] = sh[1023];
}

__global__ void scan_sums_kernel(int* bsums, int nb) {
    __shared__ int sh[128];
    int v = (threadIdx.x < nb) ? bsums[threadIdx.x] : 0;
    sh[threadIdx.x] = v;
    __syncthreads();
    for (int off = 1; off < 128; off <<= 1) {
        int t = (threadIdx.x >= off) ? sh[threadIdx.x - off] : 0;
        __syncthreads();
        sh[threadIdx.x] += t;
        __syncthreads();
    }
    if (threadIdx.x < nb) bsums[threadIdx.x] = sh[threadIdx.x] - v;
}

__global__ void add_off_kernel(int* __restrict__ rowptr, const int* __restrict__ bsums,
                               int* __restrict__ woff, int N, int E) {
    int i = blockIdx.x * blockDim.x + threadIdx.x;
    if (i < N) {
        int r = rowptr[i] + bsums[i >> 10];
        rowptr[i] = r;
        woff[i] = r;
    }
    if (i == N) rowptr[N] = E;
}

__global__ void place_kernel(const int* __restrict__ src, const int* __restrict__ dst,
                             const float* __restrict__ w, const float* __restrict__ dinv,
                             int* __restrict__ woff, int2* __restrict__ csr, int E) {
    int e = blockIdx.x * blockDim.x + threadIdx.x;
    if (e >= E) return;
    int s = src[e], d = dst[e];
    float nr = dinv[s] * w[e] * dinv[d];
    int pos = atomicAdd(&woff[d], 1);
    csr[pos] = make_int2(s, __float_as_int(nr));
}

// ---------------- CSR gather aggregation (bf16 in/out, fp32 accumulate) ----------------
template<int IN>
__global__ void gather_kernel(const int* __restrict__ rowptr, const int2* __restrict__ csr,
                              const __nv_bfloat16* __restrict__ X, const float* __restrict__ dinv,
                              __nv_bfloat16* __restrict__ Y, int N) {
    const int G = IN / 8;                 // threads per node (8 bf16 = 16B each)
    const int NPB = 256 / G;
    int lane = threadIdx.x % G;
    int node = blockIdx.x * NPB + threadIdx.x / G;
    if (node >= N) return;

    int beg = rowptr[node];
    int end = rowptr[node + 1];
    float di = dinv[node];
    float sl = di * di;

    float acc[8];
    {
        uint4 xv = *reinterpret_cast<const uint4*>(&X[(size_t)node * IN + lane * 8]);
        float xf[8]; bf8_to_f8(xv, xf);
        #pragma unroll
        for (int j = 0; j < 8; j++) acc[j] = sl * xf[j];
    }

    int k = beg;
    for (; k + 4 <= end; k += 4) {
        int2 p0 = csr[k], p1 = csr[k + 1], p2 = csr[k + 2], p3 = csr[k + 3];
        uint4 v0 = *reinterpret_cast<const uint4*>(&X[(size_t)p0.x * IN + lane * 8]);
        uint4 v1 = *reinterpret_cast<const uint4*>(&X[(size_t)p1.x * IN + lane * 8]);
        uint4 v2 = *reinterpret_cast<const uint4*>(&X[(size_t)p2.x * IN + lane * 8]);
        uint4 v3 = *reinterpret_cast<const uint4*>(&X[(size_t)p3.x * IN + lane * 8]);
        float n0 = __int_as_float(p0.y), n1 = __int_as_float(p1.y);
        float n2 = __int_as_float(p2.y), n3 = __int_as_float(p3.y);
        float f0[8], f1[8], f2[8], f3[8];
        bf8_to_f8(v0, f0); bf8_to_f8(v1, f1); bf8_to_f8(v2, f2); bf8_to_f8(v3, f3);
        #pragma unroll
        for (int j = 0; j < 8; j++)
            acc[j] += n0 * f0[j] + n1 * f1[j] + n2 * f2[j] + n3 * f3[j];
    }
    for (; k < end; k++) {
        int2 p0 = csr[k];
        float n0 = __int_as_float(p0.y);
        uint4 v0 = *reinterpret_cast<const uint4*>(&X[(size_t)p0.x * IN + lane * 8]);
        float f0[8]; bf8_to_f8(v0, f0);
        #pragma unroll
        for (int j = 0; j < 8; j++) acc[j] += n0 * f0[j];
    }

    uint4 o;
    __nv_bfloat162* q = reinterpret_cast<__nv_bfloat162*>(&o);
    #pragma unroll
    for (int j = 0; j < 4; j++) q[j] = __floats2bfloat162_rn(acc[2 * j], acc[2 * j + 1]);
    *reinterpret_cast<uint4*>(&Y[(size_t)node * IN + lane * 8]) = o;
}

// ---------------- bf16 tensor-core GEMM, cp.async double-buffered ----------------
// H = relu(A @ (Whi + Wlo) + bias), bf16 out. BM=128, BN=64, BK=32, 8 warps.
template<int OUT, int K>
__global__ void __launch_bounds__(256) bf16_gemm_kernel(
    const __nv_bfloat16* __restrict__ A, const __nv_bfloat16* __restrict__ BhiT,
    const __nv_bfloat16* __restrict__ BloT, const float* __restrict__ bias,
    __nv_bfloat16* __restrict__ Cout, int N)
{
    constexpr int NITER = K / 32;
    __shared__ __align__(16) __nv_bfloat16 As[2][128][40];
    __shared__ __align__(16) __nv_bfloat16 Bh[2][64][40];
    __shared__ __align__(16) __nv_bfloat16 Bl[2][64][40];

    int t = threadIdx.x;
    int lane = t & 31, w = t >> 5;
    int warpM = w & 3, warpN = w >> 2;
    int g = lane >> 2, tc = lane & 3;
    int rowBase = blockIdx.x * 128;
    int colBase = blockIdx.y * 64;

    // per-thread load coordinates
    int am0 = t >> 2, akq = (t & 3) * 8;          // A vec 0: row am0
    int am1 = am0 + 64;                            // A vec 1 (t+256)
    int bn = t >> 2, bkq = (t & 3) * 8;

    auto load_tile = [&](int kb, int buf) {
        const __nv_bfloat16* a0 = &A[(size_t)(rowBase + am0) * K + kb + akq];
        const __nv_bfloat16* a1 = &A[(size_t)(rowBase + am1) * K + kb + akq];
        cp_async16(&As[buf][am0][akq], (rowBase + am0 < N) ? a0 : A, (rowBase + am0 < N) ? 16 : 0);
        cp_async16(&As[buf][am1][akq], (rowBase + am1 < N) ? a1 : A, (rowBase + am1 < N) ? 16 : 0);
        cp_async16(&Bh[buf][bn][bkq], &BhiT[(size_t)(colBase + bn) * K + kb + bkq], 16);
        cp_async16(&Bl[buf][bn][bkq], &BloT[(size_t)(colBase + bn) * K + kb + bkq], 16);
    };

    float acc[2][4][4];
    #pragma unroll
    for (int a = 0; a < 2; a++)
        #pragma unroll
        for (int b = 0; b < 4; b++)
            #pragma unroll
            for (int c = 0; c < 4; c++) acc[a][b][c] = 0.0f;

    load_tile(0, 0);
    CP_COMMIT;

    #pragma unroll
    for (int it = 0; it < NITER; it++) {
        if (it + 1 < NITER) {
            load_tile((it + 1) * 32, (it + 1) & 1);
            CP_COMMIT;
            asm volatile("cp.async.wait_group 1;");
        } else {
            asm volatile("cp.async.wait_group 0;");
        }
        __syncthreads();
        int buf = it & 1;

        #pragma unroll
        for (int ks = 0; ks < 32; ks += 16) {
            uint32_t af[2][4];
            #pragma unroll
            for (int mt = 0; mt < 2; mt++) {
                int m0 = warpM * 32 + mt * 16 + g;
                af[mt][0] = *reinterpret_cast<const uint32_t*>(&As[buf][m0][ks + tc * 2]);
                af[mt][1] = *reinterpret_cast<const uint32_t*>(&As[buf][m0 + 8][ks + tc * 2]);
                af[mt][2] = *reinterpret_cast<const uint32_t*>(&As[buf][m0][ks + tc * 2 + 8]);
                af[mt][3] = *reinterpret_cast<const uint32_t*>(&As[buf][m0 + 8][ks + tc * 2 + 8]);
            }
            #pragma unroll
            for (int nt = 0; nt < 4; nt++) {
                int n0 = warpN * 32 + nt * 8 + g;
                uint32_t bh0 = *reinterpret_cast<const uint32_t*>(&Bh[buf][n0][ks + tc * 2]);
                uint32_t bh1 = *reinterpret_cast<const uint32_t*>(&Bh[buf][n0][ks + tc * 2 + 8]);
                uint32_t bl0 = *reinterpret_cast<const uint32_t*>(&Bl[buf][n0][ks + tc * 2]);
                uint32_t bl1 = *reinterpret_cast<const uint32_t*>(&Bl[buf][n0][ks + tc * 2 + 8]);
                #pragma unroll
                for (int mt = 0; mt < 2; mt++) {
                    float* c = acc[mt][nt];
                    asm volatile(
                        "mma.sync.aligned.m16n8k16.row.col.f32.bf16.bf16.f32 "
                        "{%0,%1,%2,%3}, {%4,%5,%6,%7}, {%8,%9}, {%0,%1,%2,%3};"
                        : "+f"(c[0]), "+f"(c[1]), "+f"(c[2]), "+f"(c[3])
                        : "r"(af[mt][0]), "r"(af[mt][1]), "r"(af[mt][2]), "r"(af[mt][3]),
                          "r"(bh0), "r"(bh1));
                    asm volatile(
                        "mma.sync.aligned.m16n8k16.row.col.f32.bf16.bf16.f32 "
                        "{%0,%1,%2,%3}, {%4,%5,%6,%7}, {%8,%9}, {%0,%1,%2,%3};"
                        : "+f"(c[0]), "+f"(c[1]), "+f"(c[2]), "+f"(c[3])
                        : "r"(af[mt][0]), "r"(af[mt][1]), "r"(af[mt][2]), "r"(af[mt][3]),
                          "r"(bl0), "r"(bl1));
                }
            }
        }
        __syncthreads();
    }

    // epilogue: bias + relu, bf16 out
    #pragma unroll
    for (int mt = 0; mt < 2; mt++) {
        #pragma unroll
        for (int nt = 0; nt < 4; nt++) {
            int row = rowBase + warpM * 32 + mt * 16 + g;
            int col = colBase + warpN * 32 + nt * 8 + tc * 2;
            float b0 = bias[col], b1 = bias[col + 1];
            float* c = acc[mt][nt];
            if (row < N)
                *reinterpret_cast<__nv_bfloat162*>(&Cout[(size_t)row * OUT + col]) =
                    __floats2bfloat162_rn(fmaxf(c[0] + b0, 0.f), fmaxf(c[1] + b1, 0.f));
            if (row + 8 < N)
                *reinterpret_cast<__nv_bfloat162*>(&Cout[(size_t)(row + 8) * OUT + col]) =
                    __floats2bfloat162_rn(fmaxf(c[2] + b0, 0.f), fmaxf(c[3] + b1, 0.f));
        }
    }
}

// ---------------- pooling: per-(segment, slab) streaming sums (bf16 inputs) ----------------
// grid (256 segments, 4 slabs), 240 threads = 40 8-col groups x 6 node-ways
__global__ void pool_kernel(const __nv_bfloat16* __restrict__ conv3,
                            const __nv_bfloat16* __restrict__ featb,
                            const int* __restrict__ segstart, float* __restrict__ pool) {
    __shared__ float sh[6][40][8];
    int seg = blockIdx.x, slab = blockIdx.y;
    int c = threadIdx.x % 40;
    int r = threadIdx.x / 40;            // 0..5
    int beg = segstart[seg], end = segstart[seg + 1];

    float acc[8] = {};
    for (int i = beg + slab * 6 + r; i < end; i += 24) {
        uint4 v;
        if (c < 32) v = *reinterpret_cast<const uint4*>(&conv3[(size_t)i * 256 + c * 8]);
        else        v = *reinterpret_cast<const uint4*>(&featb[(size_t)i * 64 + (c - 32) * 8]);
        float f[8]; bf8_to_f8(v, f);
        #pragma unroll
        for (int j = 0; j < 8; j++) acc[j] += f[j];
    }
    #pragma unroll
    for (int j = 0; j < 8; j++) sh[r][c][j] = acc[j];
    __syncthreads();
    if (r == 0) {
        float o[8];
        #pragma unroll
        for (int j = 0; j < 8; j++)
            o[j] = sh[0][c][j] + sh[1][c][j] + sh[2][c][j] + sh[3][c][j] + sh[4][c][j] + sh[5][c][j];
        size_t base = ((size_t)slab * 256 + seg) * 320 + c * 8;
        *reinterpret_cast<float4*>(&pool[base])     = make_float4(o[0], o[1], o[2], o[3]);
        *reinterpret_cast<float4*>(&pool[base + 4]) = make_float4(o[4], o[5], o[6], o[7]);
    }
}

// ---------------- MLP head ----------------
__global__ void fc1_kernel(const float* __restrict__ pool, const int* __restrict__ segstart,
                           const float* __restrict__ Wf1, const float* __restrict__ bf1,
                           float* __restrict__ fc1) {
    __shared__ float srow[8][320];
    __shared__ float sinv[8];
    int rowBase = blockIdx.y * 8;
    int col = blockIdx.x * 256 + threadIdx.x;

    for (int lin = threadIdx.x; lin < 8 * 320; lin += 256) {
        int rr = lin / 320, k = lin % 320;
        int row = rowBase + rr;
        float s = pool[((size_t)0 * 256 + row) * 320 + k]
                + pool[((size_t)1 * 256 + row) * 320 + k]
                + pool[((size_t)2 * 256 + row) * 320 + k]
                + pool[((size_t)3 * 256 + row) * 320 + k];
        srow[rr][k] = s;
    }
    if (threadIdx.x < 8) {
        int row = rowBase + threadIdx.x;
        int c = segstart[row + 1] - segstart[row];
        sinv[threadIdx.x] = 1.0f / fmaxf((float)c, 1.0f);
    }
    __syncthreads();

    float acc[8] = {};
    #pragma unroll 4
    for (int k = 0; k < 320; k++) {
        float wv = Wf1[(size_t)k * 1024 + col];
        #pragma unroll
        for (int rr = 0; rr < 8; rr++) acc[rr] += srow[rr][k] * wv;
    }
    float b = bf1[col];
    #pragma unroll
    for (int rr = 0; rr < 8; rr++) {
        float v = acc[rr] * sinv[rr] + b;
        fc1[(size_t)(rowBase + rr) * 1024 + col] = fmaxf(v, 0.f);
    }
}

__global__ void fc2_kernel(const float* __restrict__ fc1, const float* __restrict__ Wf2,
                           const float* __restrict__ bf2, float* __restrict__ out) {
    int row = blockIdx.x;
    float a = 0.f;
    for (int j = threadIdx.x; j < 1024; j += 256)
        a += fc1[(size_t)row * 1024 + j] * Wf2[j];
    __shared__ float red[256];
    red[threadIdx.x] = a;
    __syncthreads();
    for (int s = 128; s > 0; s >>= 1) {
        if (threadIdx.x < s) red[threadIdx.x] += red[threadIdx.x + s];
        __syncthreads();
    }
    if (threadIdx.x == 0) out[row] = red[0] + bf2[0];
}

// ---------------- launch ----------------
extern "C" void kernel_launch(void* const* d_in, const int* in_sizes, int n_in,
                              void* d_out, int out_size) {
    const float* feature = (const float*)d_in[0];
    const int*   ei      = (const int*)d_in[1];
    const float* weight  = (const float*)d_in[2];
    const int*   pb      = (const int*)d_in[3];
    const float* W1 = (const float*)d_in[4];  const float* b1  = (const float*)d_in[5];
    const float* W2 = (const float*)d_in[6];  const float* b2  = (const float*)d_in[7];
    const float* W3 = (const float*)d_in[8];  const float* b3  = (const float*)d_in[9];
    const float* Wf1 = (const float*)d_in[10]; const float* bf1 = (const float*)d_in[11];
    const float* Wf2 = (const float*)d_in[12]; const float* bf2 = (const float*)d_in[13];
    float* out = (float*)d_out;

    int N = in_sizes[0] / 64;
    int E = in_sizes[2];
    const int* src = ei;
    const int* dst = ei + E;

    float *dinv, *pool, *fc1;
    __nv_bfloat16 *actb, *bufY, *featb, *whiT, *wloT;
    float2 *dc;
    int *rowptr, *woff, *bsums, *segstart;
    int2 *csr;
    cudaGetSymbolAddress((void**)&actb, g_actb);
    cudaGetSymbolAddress((void**)&bufY, g_bufY);
    cudaGetSymbolAddress((void**)&featb, g_featb);
    cudaGetSymbolAddress((void**)&dc, g_dc);
    cudaGetSymbolAddress((void**)&dinv, g_dinv);
    cudaGetSymbolAddress((void**)&rowptr, g_rowptr);
    cudaGetSymbolAddress((void**)&woff, g_woff);
    cudaGetSymbolAddress((void**)&bsums, g_bsums);
    cudaGetSymbolAddress((void**)&csr, g_csr);
    cudaGetSymbolAddress((void**)&segstart, g_segstart);
    cudaGetSymbolAddress((void**)&whiT, g_whiT);
    cudaGetSymbolAddress((void**)&wloT, g_wloT);
    cudaGetSymbolAddress((void**)&pool, g_pool);
    cudaGetSymbolAddress((void**)&fc1,  g_fc1);

    const int T = 256;
    int nb = (N + 1023) / 1024;
    int nWS = (45056 + 255) / 256;
    int nFC = (N * 16 + 255) / 256;
    int nDI = (N + 255) / 256;

    // fused prep: wsplit | featcvt | seg_bounds | deg_init
    prep_kernel<<<nWS + nFC + 2 + nDI, T>>>(W1, W2, W3, whiT, wloT, feature, featb,
                                            pb, segstart, dc, N, nWS, nFC);
    deg_acc_kernel<<<(E + T - 1) / T, T>>>(dst, weight, dc, E);
    scan_block_kernel<<<nb, 1024>>>(dc, rowptr, bsums, dinv, N);
    scan_sums_kernel<<<1, 128>>>(bsums, nb);
    add_off_kernel<<<(N + 1 + T - 1) / T, T>>>(rowptr, bsums, woff, N, E);
    place_kernel<<<(E + T - 1) / T, T>>>(src, dst, weight, dinv, woff, csr, E);

    int gb128 = (N + 127) / 128;

    // layer 1: [N,64] -> [N,64]
    gather_kernel<64><<<(N * 8 + 255) / 256, 256>>>(rowptr, csr, featb, dinv, bufY, N);
    bf16_gemm_kernel<64, 64><<<dim3(gb128, 1), 256>>>(bufY, whiT, wloT, b1, actb, N);

    // layer 2: [N,64] -> [N,128]
    gather_kernel<64><<<(N * 8 + 255) / 256, 256>>>(rowptr, csr, actb, dinv, bufY, N);
    bf16_gemm_kernel<128, 64><<<dim3(gb128, 2), 256>>>(bufY, whiT + 4096, wloT + 4096, b2, actb, N);

    // layer 3: [N,128] -> [N,256]  (h2 in actb is consumed into bufY before overwrite)
    gather_kernel<128><<<(N * 16 + 255) / 256, 256>>>(rowptr, csr, actb, dinv, bufY, N);
    bf16_gemm_kernel<256, 128><<<dim3(gb128, 4), 256>>>(bufY, whiT + 12288, wloT + 12288, b3, actb, N);

    // pooling + MLP head
    pool_kernel<<<dim3(256, 4), 240>>>(actb, featb, segstart, pool);
    fc1_kernel<<<dim3(4, 32), 256>>>(pool, segstart, Wf1, bf1, fc1);
    fc2_kernel<<<256, 256>>>(fc1, Wf2, bf2, out);
}